// round 11
// baseline (speedup 1.0000x reference)
#include <cuda_runtime.h>
#include <cuda_fp16.h>
#include <math.h>
#include <stdint.h>

// Problem constants
#define Bq 64
#define Aq 256
#define Hq 512
#define Oq 2
#define Tq 32
#define Nq (Bq*Aq)     // 16384 rows
#define G3 (3*Hq)      // 1536
#define MH (Hq/2)      // 256

// ---------------- device globals (no allocation allowed) --------------------
__device__ float g_h0[Nq*Hq];
__device__ float g_h1[Nq*Hq];
__device__ __half g_h0h[Nq*Hq];    // fp16 copy of h0
__device__ __half g_h1h[Nq*Hq];    // fp16 copy of h1
__device__ float g_gate0[Nq*G3];
__device__ float g_gate1[Nq*G3];
__device__ float g_x[Nq*Oq];
__device__ float g_m[Nq*MH];
__device__ __half g_Whh0hi[G3*Hq], g_Whh0lo[G3*Hq];
__device__ __half g_Wih1hi[G3*Hq], g_Wih1lo[G3*Hq];
__device__ __half g_Whh1hi[G3*Hq], g_Whh1lo[G3*Hq];
__device__ __half g_W1hi[MH*Hq],  g_W1lo[MH*Hq];

// ---------------- helpers ----------------------------------------------------
__device__ __forceinline__ uint32_t smem_u32(const void* p) {
    uint32_t a;
    asm("{ .reg .u64 t; cvta.to.shared.u64 t, %1; cvt.u32.u64 %0, t; }" : "=r"(a) : "l"(p));
    return a;
}
__device__ __forceinline__ void cp_async16(uint32_t dst, const void* src) {
    asm volatile("cp.async.cg.shared.global [%0], [%1], 16;" :: "r"(dst), "l"(src) : "memory");
}
__device__ __forceinline__ void ldmatrix_x4(uint32_t& r0, uint32_t& r1, uint32_t& r2, uint32_t& r3, uint32_t addr) {
    asm volatile("ldmatrix.sync.aligned.m8n8.x4.shared.b16 {%0,%1,%2,%3}, [%4];"
                 : "=r"(r0), "=r"(r1), "=r"(r2), "=r"(r3) : "r"(addr));
}
__device__ __forceinline__ void mma16816(float* d, uint32_t a0, uint32_t a1, uint32_t a2, uint32_t a3,
                                         uint32_t b0, uint32_t b1) {
    asm volatile("mma.sync.aligned.m16n8k16.row.col.f32.f16.f16.f32 "
                 "{%0,%1,%2,%3}, {%4,%5,%6,%7}, {%8,%9}, {%0,%1,%2,%3};"
                 : "+f"(d[0]), "+f"(d[1]), "+f"(d[2]), "+f"(d[3])
                 : "r"(a0), "r"(a1), "r"(a2), "r"(a3), "r"(b0), "r"(b1));
}

// ---------------- GEMM (mma.sync fp16, 2-pass hi/lo weight split) ------------
// C[Nq x M] = A[Nq x 512] @ (Whi + Wlo)[M x 512]^T   with A = fp16(act)
// R10 config: tile 128x128, 8 warps as 4 row-groups x 2 col-groups (32x64
// warp tile), K chunks of 64 halves, 3-stage cp.async pipeline with a single
// __syncthreads per chunk, 2 CTAs/SM.
// Triple-problem: blockIdx.z selects one of 3 independent GEMM problems
// (wave-tail packing). CTAs with colBase >= M exit immediately (allows a
// smaller problem, e.g. the MLP, to ride in a wide launch).
#define BM 128
#define BN 128
#define BKH 64                      // halves per chunk
#define ROWB 144                    // smem row stride bytes (72 halves, padded)
#define STAGE_BYTES ((BM + BN) * ROWB)   // 36864
#define NSTAGE 3
#define GEMM_SMEM (NSTAGE * STAGE_BYTES) // 110592
#define NSEG 2
#define NCH (NSEG * 8)              // 16 chunks

struct GemmSegs {
    const __half* a[NSEG];
    const __half* w[NSEG];
};
struct GemmProb {
    GemmSegs segs;
    float* C;
    int M;
    const float* bias;
    int relu;
};

__global__ __launch_bounds__(256, 2) void gemm_mma(
    GemmProb p0, GemmProb p1, GemmProb p2)
{
    extern __shared__ char sm[];
    const GemmProb& p = (blockIdx.z == 0) ? p0 : (blockIdx.z == 1) ? p1 : p2;
    const int colBase = blockIdx.x * BN;
    if (colBase >= p.M) return;              // idle guard for small problems

    const int tid  = threadIdx.x;
    const int warp = tid >> 5;
    const int lane = tid & 31;
    const int rowBase = blockIdx.y * BM;
    const int wr = (warp & 3) * 32;      // warp row offset (0/32/64/96)
    const int wc = (warp >> 2) * 64;     // warp col offset (0/64)

    const GemmSegs& segs = p.segs;
    float* __restrict__ C = p.C;
    const int M = p.M;
    const float* __restrict__ bias = p.bias;
    const int relu = p.relu;

    const uint32_t sbase = smem_u32(sm);

    float acc[2][8][4];
#pragma unroll
    for (int i = 0; i < 2; i++)
#pragma unroll
        for (int j = 0; j < 8; j++)
#pragma unroll
            for (int v = 0; v < 4; v++) acc[i][j][v] = 0.0f;

    // ---- chunk loader: each thread copies 4 A row-segments + 4 W -----------
#define LOAD_CHUNK(c, s) do { \
        int _seg  = (c) >> 3; \
        int _koff = ((c) & 7) * BKH; \
        const __half* _Ag = segs.a[_seg] + (size_t)rowBase * Hq + _koff; \
        const __half* _Wg = segs.w[_seg] + (size_t)colBase * Hq + _koff; \
        uint32_t _ab = sbase + (s) * STAGE_BYTES; \
        uint32_t _wb = _ab + BM * ROWB; \
        _Pragma("unroll") \
        for (int _i = 0; _i < 4; _i++) { \
            int _lin = tid + _i * 256; \
            int _r = _lin >> 3, _sg = _lin & 7; \
            cp_async16(_ab + _r * ROWB + _sg * 16, _Ag + (size_t)_r * Hq + _sg * 8); \
            cp_async16(_wb + _r * ROWB + _sg * 16, _Wg + (size_t)_r * Hq + _sg * 8); \
        } \
        asm volatile("cp.async.commit_group;" ::: "memory"); \
    } while (0)

    LOAD_CHUNK(0, 0);
    LOAD_CHUNK(1, 1);

    // ldmatrix base addresses (stage offset added in loop)
    const uint32_t aAddrBase = (wr + (lane & 15)) * ROWB + (lane >> 4) * 16;
    const uint32_t wAddrBase = BM * ROWB
        + (wc + (lane & 7) + ((lane >> 4) & 1) * 8) * ROWB
        + ((lane >> 3) & 1) * 16;

    for (int c = 0; c < NCH; c++) {
        if (c + 1 < NCH) {
            asm volatile("cp.async.wait_group 1;" ::: "memory");
        } else {
            asm volatile("cp.async.wait_group 0;" ::: "memory");
        }
        __syncthreads();   // all warps done with chunk c-1 MMAs; stage (c+2)%3 free

        if (c + 2 < NCH) LOAD_CHUNK(c + 2, (c + 2) % NSTAGE);

        const uint32_t stageOff = sbase + (c % NSTAGE) * STAGE_BYTES;
#pragma unroll
        for (int ks = 0; ks < 4; ks++) {
            uint32_t af[2][4], bf[4][4];
#pragma unroll
            for (int rt = 0; rt < 2; rt++)
                ldmatrix_x4(af[rt][0], af[rt][1], af[rt][2], af[rt][3],
                            stageOff + aAddrBase + rt * 16 * ROWB + ks * 32);
#pragma unroll
            for (int cp = 0; cp < 4; cp++)
                ldmatrix_x4(bf[cp][0], bf[cp][1], bf[cp][2], bf[cp][3],
                            stageOff + wAddrBase + cp * 16 * ROWB + ks * 32);
#pragma unroll
            for (int rt = 0; rt < 2; rt++)
#pragma unroll
                for (int ct = 0; ct < 8; ct++) {
                    int cp = ct >> 1, hf = (ct & 1) * 2;
                    mma16816(acc[rt][ct], af[rt][0], af[rt][1], af[rt][2], af[rt][3],
                             bf[cp][hf], bf[cp][hf + 1]);
                }
        }
    }

    // ---- epilogue ----
    const int gid = lane >> 2;
    const int tig = lane & 3;
#pragma unroll
    for (int rt = 0; rt < 2; rt++) {
        int row0 = rowBase + wr + rt * 16 + gid;
#pragma unroll
        for (int ct = 0; ct < 8; ct++) {
            int col = colBase + wc + ct * 8 + tig * 2;
            float2 v0 = make_float2(acc[rt][ct][0], acc[rt][ct][1]);
            float2 v1 = make_float2(acc[rt][ct][2], acc[rt][ct][3]);
            if (bias) {
                float b0 = bias[col], b1 = bias[col + 1];
                v0.x += b0; v0.y += b1; v1.x += b0; v1.y += b1;
            }
            if (relu) {
                v0.x = fmaxf(v0.x, 0.f); v0.y = fmaxf(v0.y, 0.f);
                v1.x = fmaxf(v1.x, 0.f); v1.y = fmaxf(v1.y, 0.f);
            }
            *reinterpret_cast<float2*>(C + (size_t)row0 * M + col) = v0;
            *reinterpret_cast<float2*>(C + (size_t)(row0 + 8) * M + col) = v1;
        }
    }
#undef LOAD_CHUNK
}

// ---------------- fused weight split (fp16 hi/lo, all 4 weights) -------------
#define WSZ (G3*Hq)          // 786432
#define SPLIT_TOTAL (3*WSZ + MH*Hq)
__global__ void split_all(const float* __restrict__ Whh0, const float* __restrict__ Wih1,
                          const float* __restrict__ Whh1, const float* __restrict__ W1)
{
    int idx = blockIdx.x * blockDim.x + threadIdx.x;
    if (idx >= SPLIT_TOTAL) return;
    const float* src; __half* hi; __half* lo; int i;
    if (idx < WSZ)            { src = Whh0; hi = g_Whh0hi; lo = g_Whh0lo; i = idx; }
    else if (idx < 2*WSZ)     { src = Wih1; hi = g_Wih1hi; lo = g_Wih1lo; i = idx - WSZ; }
    else if (idx < 3*WSZ)     { src = Whh1; hi = g_Whh1hi; lo = g_Whh1lo; i = idx - 2*WSZ; }
    else                      { src = W1;   hi = g_W1hi;   lo = g_W1lo;   i = idx - 3*WSZ; }
    float v = src[i];
    __half h = __float2half_rn(v);
    hi[i] = h;
    lo[i] = __float2half_rn(v - __half2float(h));
}

// ---------------- init -------------------------------------------------------
// hidden row i = a*B + b holds social[b][a]
__global__ void init_kernel(const float* __restrict__ social,
                            const float* __restrict__ lastpos)
{
    int idx = blockIdx.x * blockDim.x + threadIdx.x;
    if (idx < Nq * Hq) {
        int i = idx >> 9;
        int cch = idx & (Hq - 1);
        int b = i & (Bq - 1);
        int a = i >> 6;
        float v = social[(b * Aq + a) * Hq + cch];
        g_h0[idx] = v;
        g_h1[idx] = v;
        __half h = __float2half_rn(v);
        g_h0h[idx] = h;
        g_h1h[idx] = h;
    }
    if (idx < Nq * Oq) g_x[idx] = lastpos[idx];
}

// ---------------- GRU combine layer 0 (vectorized x4, inline x@Wih0) ---------
__global__ __launch_bounds__(256, 3) void combine0(
                         const float* __restrict__ gh,
                         float* __restrict__ h,
                         __half* __restrict__ hh,
                         const float* __restrict__ Wih0,
                         const float* __restrict__ bih,
                         const float* __restrict__ bhh)
{
    int v4 = blockIdx.x * blockDim.x + threadIdx.x;   // Nq*Hq/4 threads
    if (v4 >= Nq * Hq / 4) return;
    int idx = v4 * 4;
    int i = idx >> 9;
    int j = idx & (Hq - 1);

    float x0 = g_x[i * 2 + 0];
    float x1 = g_x[i * 2 + 1];

    const float* g = gh + (size_t)i * G3;
    float4 gr = *(const float4*)(g + 0 * Hq + j);
    float4 gz = *(const float4*)(g + 1 * Hq + j);
    float4 gn = *(const float4*)(g + 2 * Hq + j);
    float4 br_i = *(const float4*)(bih + 0 * Hq + j);
    float4 bz_i = *(const float4*)(bih + 1 * Hq + j);
    float4 bn_i = *(const float4*)(bih + 2 * Hq + j);
    float4 br_h = *(const float4*)(bhh + 0 * Hq + j);
    float4 bz_h = *(const float4*)(bhh + 1 * Hq + j);
    float4 bn_h = *(const float4*)(bhh + 2 * Hq + j);
    float4 hp = *(const float4*)(h + idx);

    float4 wr0 = *(const float4*)(Wih0 + (0 * Hq + j) * 2);
    float4 wr1 = *(const float4*)(Wih0 + (0 * Hq + j) * 2 + 4);
    float4 wz0 = *(const float4*)(Wih0 + (1 * Hq + j) * 2);
    float4 wz1 = *(const float4*)(Wih0 + (1 * Hq + j) * 2 + 4);
    float4 wn0 = *(const float4*)(Wih0 + (2 * Hq + j) * 2);
    float4 wn1 = *(const float4*)(Wih0 + (2 * Hq + j) * 2 + 4);

    float ho[4]; __half hhv[4];
#pragma unroll
    for (int u = 0; u < 4; u++) {
        float wir0 = (u < 2) ? ((u == 0) ? wr0.x : wr0.z) : ((u == 2) ? wr1.x : wr1.z);
        float wir1 = (u < 2) ? ((u == 0) ? wr0.y : wr0.w) : ((u == 2) ? wr1.y : wr1.w);
        float wiz0 = (u < 2) ? ((u == 0) ? wz0.x : wz0.z) : ((u == 2) ? wz1.x : wz1.z);
        float wiz1 = (u < 2) ? ((u == 0) ? wz0.y : wz0.w) : ((u == 2) ? wz1.y : wz1.w);
        float win0 = (u < 2) ? ((u == 0) ? wn0.x : wn0.z) : ((u == 2) ? wn1.x : wn1.z);
        float win1 = (u < 2) ? ((u == 0) ? wn0.y : wn0.w) : ((u == 2) ? wn1.y : wn1.w);

        float grv = (&gr.x)[u], gzv = (&gz.x)[u], gnv = (&gn.x)[u];
        float ir  = x0 * wir0 + x1 * wir1 + (&br_i.x)[u];
        float iz  = x0 * wiz0 + x1 * wiz1 + (&bz_i.x)[u];
        float in_ = x0 * win0 + x1 * win1 + (&bn_i.x)[u];
        float hr = grv + (&br_h.x)[u];
        float hz = gzv + (&bz_h.x)[u];
        float hn = gnv + (&bn_h.x)[u];

        float r = 1.0f / (1.0f + expf(-(ir + hr)));
        float z = 1.0f / (1.0f + expf(-(iz + hz)));
        float n = tanhf(in_ + r * hn);
        float v = (1.0f - z) * n + z * (&hp.x)[u];
        ho[u] = v;
        hhv[u] = __float2half_rn(v);
    }
    *(float4*)(h + idx) = make_float4(ho[0], ho[1], ho[2], ho[3]);
    *(uint2*)(hh + idx) = *(uint2*)hhv;
}

// ---------------- GRU combine layer 1 (vectorized x4) ------------------------
__global__ __launch_bounds__(256, 3) void combine1(
                         const float* __restrict__ gi,
                         const float* __restrict__ gh,
                         float* __restrict__ h,
                         __half* __restrict__ hh,
                         const float* __restrict__ bih,
                         const float* __restrict__ bhh)
{
    int v4 = blockIdx.x * blockDim.x + threadIdx.x;
    if (v4 >= Nq * Hq / 4) return;
    int idx = v4 * 4;
    int i = idx >> 9;
    int j = idx & (Hq - 1);

    const float* a = gi + (size_t)i * G3;
    const float* g = gh + (size_t)i * G3;

    float4 ar = *(const float4*)(a + 0 * Hq + j);
    float4 az = *(const float4*)(a + 1 * Hq + j);
    float4 an = *(const float4*)(a + 2 * Hq + j);
    float4 gr = *(const float4*)(g + 0 * Hq + j);
    float4 gz = *(const float4*)(g + 1 * Hq + j);
    float4 gn = *(const float4*)(g + 2 * Hq + j);
    float4 br_i = *(const float4*)(bih + 0 * Hq + j);
    float4 bz_i = *(const float4*)(bih + 1 * Hq + j);
    float4 bn_i = *(const float4*)(bih + 2 * Hq + j);
    float4 br_h = *(const float4*)(bhh + 0 * Hq + j);
    float4 bz_h = *(const float4*)(bhh + 1 * Hq + j);
    float4 bn_h = *(const float4*)(bhh + 2 * Hq + j);
    float4 hp = *(const float4*)(h + idx);

    float ho[4]; __half hhv[4];
#pragma unroll
    for (int u = 0; u < 4; u++) {
        float ir  = (&ar.x)[u] + (&br_i.x)[u];
        float iz  = (&az.x)[u] + (&bz_i.x)[u];
        float in_ = (&an.x)[u] + (&bn_i.x)[u];
        float hr  = (&gr.x)[u] + (&br_h.x)[u];
        float hz  = (&gz.x)[u] + (&bz_h.x)[u];
        float hn  = (&gn.x)[u] + (&bn_h.x)[u];

        float r = 1.0f / (1.0f + expf(-(ir + hr)));
        float z = 1.0f / (1.0f + expf(-(iz + hz)));
        float n = tanhf(in_ + r * hn);
        float v = (1.0f - z) * n + z * (&hp.x)[u];
        ho[u] = v;
        hhv[u] = __float2half_rn(v);
    }
    *(float4*)(h + idx) = make_float4(ho[0], ho[1], ho[2], ho[3]);
    *(uint2*)(hh + idx) = *(uint2*)hhv;
}

// ---------------- prediction: pred = Mh @ W2^T + b2 --------------------------
__global__ void pred_kernel(const float* __restrict__ Mh,
                            const float* __restrict__ W2,
                            const float* __restrict__ b2,
                            float* __restrict__ out, int t)
{
    int gwarp = (blockIdx.x * blockDim.x + threadIdx.x) >> 5;
    int lane  = threadIdx.x & 31;
    if (gwarp >= Nq) return;

    const float* mrow = Mh + (size_t)gwarp * MH;
    float s0 = 0.0f, s1 = 0.0f;
#pragma unroll
    for (int u = 0; u < 8; u++) {
        float m = mrow[lane + 32 * u];
        s0 = fmaf(m, W2[      lane + 32 * u], s0);
        s1 = fmaf(m, W2[MH +  lane + 32 * u], s1);
    }
#pragma unroll
    for (int off = 16; off; off >>= 1) {
        s0 += __shfl_xor_sync(0xFFFFFFFFu, s0, off);
        s1 += __shfl_xor_sync(0xFFFFFFFFu, s1, off);
    }
    if (lane == 0) {
        s0 += b2[0];
        s1 += b2[1];
        g_x[gwarp * 2 + 0] = s0;
        g_x[gwarp * 2 + 1] = s1;
        int b = gwarp >> 8;
        int a = gwarp & (Aq - 1);
        float* o = out + (((size_t)b * Tq + t) * Aq + a) * Oq;
        o[0] = s0;
        o[1] = s1;
    }
}

// ---------------- launch -----------------------------------------------------
extern "C" void kernel_launch(void* const* d_in, const int* in_sizes, int n_in,
                              void* d_out, int out_size)
{
    const float* social  = (const float*)d_in[0];
    const float* lastpos = (const float*)d_in[1];
    const float* Wih0    = (const float*)d_in[2];
    const float* Whh0    = (const float*)d_in[3];
    const float* bih0    = (const float*)d_in[4];
    const float* bhh0    = (const float*)d_in[5];
    const float* Wih1    = (const float*)d_in[6];
    const float* Whh1    = (const float*)d_in[7];
    const float* bih1    = (const float*)d_in[8];
    const float* bhh1    = (const float*)d_in[9];
    const float* W1      = (const float*)d_in[10];
    const float* b1      = (const float*)d_in[11];
    const float* W2      = (const float*)d_in[12];
    const float* b2      = (const float*)d_in[13];
    float* out = (float*)d_out;

    float *h0, *h1, *gate0, *gate1, *mbuf;
    __half *h0h, *h1h;
    __half *whh0hi, *whh0lo, *wih1hi, *wih1lo, *whh1hi, *whh1lo, *w1hi, *w1lo;
    cudaGetSymbolAddress((void**)&h0,    g_h0);
    cudaGetSymbolAddress((void**)&h1,    g_h1);
    cudaGetSymbolAddress((void**)&gate0, g_gate0);
    cudaGetSymbolAddress((void**)&gate1, g_gate1);
    cudaGetSymbolAddress((void**)&mbuf,  g_m);
    cudaGetSymbolAddress((void**)&h0h,   g_h0h);
    cudaGetSymbolAddress((void**)&h1h,   g_h1h);
    cudaGetSymbolAddress((void**)&whh0hi, g_Whh0hi);
    cudaGetSymbolAddress((void**)&whh0lo, g_Whh0lo);
    cudaGetSymbolAddress((void**)&wih1hi, g_Wih1hi);
    cudaGetSymbolAddress((void**)&wih1lo, g_Wih1lo);
    cudaGetSymbolAddress((void**)&whh1hi, g_Whh1hi);
    cudaGetSymbolAddress((void**)&whh1lo, g_Whh1lo);
    cudaGetSymbolAddress((void**)&w1hi,  g_W1hi);
    cudaGetSymbolAddress((void**)&w1lo,  g_W1lo);

    cudaFuncSetAttribute(gemm_mma, cudaFuncAttributeMaxDynamicSharedMemorySize, GEMM_SMEM);

    // split weights (fused, idempotent, every call)
    split_all<<<(SPLIT_TOTAL + 255) / 256, 256>>>(Whh0, Wih1, Whh1, W1);

    init_kernel<<<(Nq * Hq + 255) / 256, 256>>>(social, lastpos);

    // GEMM problem descriptors
    GemmProb pGh0; pGh0.segs.a[0] = h0h; pGh0.segs.a[1] = h0h;
                   pGh0.segs.w[0] = whh0hi; pGh0.segs.w[1] = whh0lo;
                   pGh0.C = gate0; pGh0.M = G3; pGh0.bias = nullptr; pGh0.relu = 0;
    GemmProb pGh1; pGh1.segs.a[0] = h1h; pGh1.segs.a[1] = h1h;
                   pGh1.segs.w[0] = whh1hi; pGh1.segs.w[1] = whh1lo;
                   pGh1.C = gate1; pGh1.M = G3; pGh1.bias = nullptr; pGh1.relu = 0;
    GemmProb pGi1; pGi1.segs.a[0] = h0h; pGi1.segs.a[1] = h0h;
                   pGi1.segs.w[0] = wih1hi; pGi1.segs.w[1] = wih1lo;
                   pGi1.C = gate0; pGi1.M = G3; pGi1.bias = nullptr; pGi1.relu = 0;
    GemmProb pMlp; pMlp.segs.a[0] = h1h; pMlp.segs.a[1] = h1h;
                   pMlp.segs.w[0] = w1hi; pMlp.segs.w[1] = w1lo;
                   pMlp.C = mbuf; pMlp.M = MH; pMlp.bias = b1; pMlp.relu = 1;

    dim3 gridDual(G3 / BN, Nq / BM, 2);   // 12 x 128 x 2
    dim3 gridTri(G3 / BN, Nq / BM, 3);    // 12 x 128 x 3 (z=2: MLP, 2 live x-blocks)
    dim3 gridSingle(G3 / BN, Nq / BM, 1); // 12 x 128
    dim3 gridMlp(MH / BN, Nq / BM, 1);    // 2 x 128
    int combBlocks = (Nq * Hq / 4 + 255) / 256;

    // step 0 gates (no previous-step MLP to fold in)
    gemm_mma<<<gridDual, 256, GEMM_SMEM>>>(pGh0, pGh1, pGh1);

    for (int t = 0; t < Tq; t++) {
        combine0<<<combBlocks, 256>>>(gate0, h0, h0h, Wih0, bih0, bhh0);

        // Gi1 = h0n @ Wih1^T
        gemm_mma<<<gridSingle, 256, GEMM_SMEM>>>(pGi1, pGi1, pGi1);
        combine1<<<combBlocks, 256>>>(gate0, gate1, h1, h1h, bih1, bhh1);

        if (t + 1 < Tq) {
            // fold MLP(t) into next step's dual gate launch (independent work)
            gemm_mma<<<gridTri, 256, GEMM_SMEM>>>(pGh0, pGh1, pMlp);
        } else {
            gemm_mma<<<gridMlp, 256, GEMM_SMEM>>>(pMlp, pMlp, pMlp);
        }
        pred_kernel<<<Nq * 32 / 256, 256>>>(mbuf, W2, b2, out, t);
    }
}

// round 12
// speedup vs baseline: 1.0102x; 1.0102x over previous
#include <cuda_runtime.h>
#include <cuda_fp16.h>
#include <math.h>
#include <stdint.h>

// Problem constants
#define Bq 64
#define Aq 256
#define Hq 512
#define Oq 2
#define Tq 32
#define Nq (Bq*Aq)     // 16384 rows
#define G3 (3*Hq)      // 1536
#define MH (Hq/2)      // 256

// ---------------- device globals (no allocation allowed) --------------------
__device__ float g_h0[Nq*Hq];
__device__ float g_h1[Nq*Hq];
__device__ __half g_h0h[Nq*Hq];    // fp16 copy of h0
__device__ __half g_h1h[Nq*Hq];    // fp16 copy of h1
__device__ float g_gate0[Nq*G3];
__device__ float g_gate1[Nq*G3];
__device__ float g_x[Nq*Oq];
__device__ float g_m[Nq*MH];
__device__ __half g_Whh0hi[G3*Hq], g_Whh0lo[G3*Hq];
__device__ __half g_Wih1hi[G3*Hq], g_Wih1lo[G3*Hq];
__device__ __half g_Whh1hi[G3*Hq], g_Whh1lo[G3*Hq];
__device__ __half g_W1hi[MH*Hq],  g_W1lo[MH*Hq];

// ---------------- helpers ----------------------------------------------------
__device__ __forceinline__ uint32_t smem_u32(const void* p) {
    uint32_t a;
    asm("{ .reg .u64 t; cvta.to.shared.u64 t, %1; cvt.u32.u64 %0, t; }" : "=r"(a) : "l"(p));
    return a;
}
__device__ __forceinline__ void cp_async16(uint32_t dst, const void* src) {
    asm volatile("cp.async.cg.shared.global [%0], [%1], 16;" :: "r"(dst), "l"(src) : "memory");
}
__device__ __forceinline__ void ldmatrix_x4(uint32_t& r0, uint32_t& r1, uint32_t& r2, uint32_t& r3, uint32_t addr) {
    asm volatile("ldmatrix.sync.aligned.m8n8.x4.shared.b16 {%0,%1,%2,%3}, [%4];"
                 : "=r"(r0), "=r"(r1), "=r"(r2), "=r"(r3) : "r"(addr));
}
__device__ __forceinline__ void mma16816(float* d, uint32_t a0, uint32_t a1, uint32_t a2, uint32_t a3,
                                         uint32_t b0, uint32_t b1) {
    asm volatile("mma.sync.aligned.m16n8k16.row.col.f32.f16.f16.f32 "
                 "{%0,%1,%2,%3}, {%4,%5,%6,%7}, {%8,%9}, {%0,%1,%2,%3};"
                 : "+f"(d[0]), "+f"(d[1]), "+f"(d[2]), "+f"(d[3])
                 : "r"(a0), "r"(a1), "r"(a2), "r"(a3), "r"(b0), "r"(b1));
}

// ---------------- GEMM (mma.sync fp16, 2-pass hi/lo weight split) ------------
// C[Nq x M] = A[Nq x 512] @ (Whi + Wlo)[M x 512]^T   with A = fp16(act)
// R10 config: tile 128x128, 8 warps as 4 row-groups x 2 col-groups (32x64
// warp tile), K chunks of 64 halves, 3-stage cp.async pipeline with a single
// __syncthreads per chunk, 2 CTAs/SM.
// Dual/triple-problem: blockIdx.z selects one of 3 independent GEMM problems
// (wave-tail packing of independent GEMMs of the same shape).
#define BM 128
#define BN 128
#define BKH 64                      // halves per chunk
#define ROWB 144                    // smem row stride bytes (72 halves, padded)
#define STAGE_BYTES ((BM + BN) * ROWB)   // 36864
#define NSTAGE 3
#define GEMM_SMEM (NSTAGE * STAGE_BYTES) // 110592
#define NSEG 2
#define NCH (NSEG * 8)              // 16 chunks

struct GemmSegs {
    const __half* a[NSEG];
    const __half* w[NSEG];
};
struct GemmProb {
    GemmSegs segs;
    float* C;
    int M;
    const float* bias;
    int relu;
};

__global__ __launch_bounds__(256, 2) void gemm_mma(
    GemmProb p0, GemmProb p1, GemmProb p2)
{
    extern __shared__ char sm[];
    const GemmProb& p = (blockIdx.z == 0) ? p0 : (blockIdx.z == 1) ? p1 : p2;
    const int colBase = blockIdx.x * BN;
    if (colBase >= p.M) return;              // idle guard for small problems

    const int tid  = threadIdx.x;
    const int warp = tid >> 5;
    const int lane = tid & 31;
    const int rowBase = blockIdx.y * BM;
    const int wr = (warp & 3) * 32;      // warp row offset (0/32/64/96)
    const int wc = (warp >> 2) * 64;     // warp col offset (0/64)

    const GemmSegs& segs = p.segs;
    float* __restrict__ C = p.C;
    const int M = p.M;
    const float* __restrict__ bias = p.bias;
    const int relu = p.relu;

    const uint32_t sbase = smem_u32(sm);

    float acc[2][8][4];
#pragma unroll
    for (int i = 0; i < 2; i++)
#pragma unroll
        for (int j = 0; j < 8; j++)
#pragma unroll
            for (int v = 0; v < 4; v++) acc[i][j][v] = 0.0f;

    // ---- chunk loader: each thread copies 4 A row-segments + 4 W -----------
#define LOAD_CHUNK(c, s) do { \
        int _seg  = (c) >> 3; \
        int _koff = ((c) & 7) * BKH; \
        const __half* _Ag = segs.a[_seg] + (size_t)rowBase * Hq + _koff; \
        const __half* _Wg = segs.w[_seg] + (size_t)colBase * Hq + _koff; \
        uint32_t _ab = sbase + (s) * STAGE_BYTES; \
        uint32_t _wb = _ab + BM * ROWB; \
        _Pragma("unroll") \
        for (int _i = 0; _i < 4; _i++) { \
            int _lin = tid + _i * 256; \
            int _r = _lin >> 3, _sg = _lin & 7; \
            cp_async16(_ab + _r * ROWB + _sg * 16, _Ag + (size_t)_r * Hq + _sg * 8); \
            cp_async16(_wb + _r * ROWB + _sg * 16, _Wg + (size_t)_r * Hq + _sg * 8); \
        } \
        asm volatile("cp.async.commit_group;" ::: "memory"); \
    } while (0)

    LOAD_CHUNK(0, 0);
    LOAD_CHUNK(1, 1);

    // ldmatrix base addresses (stage offset added in loop)
    const uint32_t aAddrBase = (wr + (lane & 15)) * ROWB + (lane >> 4) * 16;
    const uint32_t wAddrBase = BM * ROWB
        + (wc + (lane & 7) + ((lane >> 4) & 1) * 8) * ROWB
        + ((lane >> 3) & 1) * 16;

    for (int c = 0; c < NCH; c++) {
        if (c + 1 < NCH) {
            asm volatile("cp.async.wait_group 1;" ::: "memory");
        } else {
            asm volatile("cp.async.wait_group 0;" ::: "memory");
        }
        __syncthreads();   // all warps done with chunk c-1 MMAs; stage (c+2)%3 free

        if (c + 2 < NCH) LOAD_CHUNK(c + 2, (c + 2) % NSTAGE);

        const uint32_t stageOff = sbase + (c % NSTAGE) * STAGE_BYTES;
#pragma unroll
        for (int ks = 0; ks < 4; ks++) {
            uint32_t af[2][4], bf[4][4];
#pragma unroll
            for (int rt = 0; rt < 2; rt++)
                ldmatrix_x4(af[rt][0], af[rt][1], af[rt][2], af[rt][3],
                            stageOff + aAddrBase + rt * 16 * ROWB + ks * 32);
#pragma unroll
            for (int cp = 0; cp < 4; cp++)
                ldmatrix_x4(bf[cp][0], bf[cp][1], bf[cp][2], bf[cp][3],
                            stageOff + wAddrBase + cp * 16 * ROWB + ks * 32);
#pragma unroll
            for (int rt = 0; rt < 2; rt++)
#pragma unroll
                for (int ct = 0; ct < 8; ct++) {
                    int cp = ct >> 1, hf = (ct & 1) * 2;
                    mma16816(acc[rt][ct], af[rt][0], af[rt][1], af[rt][2], af[rt][3],
                             bf[cp][hf], bf[cp][hf + 1]);
                }
        }
    }

    // ---- epilogue ----
    const int gid = lane >> 2;
    const int tig = lane & 3;
#pragma unroll
    for (int rt = 0; rt < 2; rt++) {
        int row0 = rowBase + wr + rt * 16 + gid;
#pragma unroll
        for (int ct = 0; ct < 8; ct++) {
            int col = colBase + wc + ct * 8 + tig * 2;
            float2 v0 = make_float2(acc[rt][ct][0], acc[rt][ct][1]);
            float2 v1 = make_float2(acc[rt][ct][2], acc[rt][ct][3]);
            if (bias) {
                float b0 = bias[col], b1 = bias[col + 1];
                v0.x += b0; v0.y += b1; v1.x += b0; v1.y += b1;
            }
            if (relu) {
                v0.x = fmaxf(v0.x, 0.f); v0.y = fmaxf(v0.y, 0.f);
                v1.x = fmaxf(v1.x, 0.f); v1.y = fmaxf(v1.y, 0.f);
            }
            *reinterpret_cast<float2*>(C + (size_t)row0 * M + col) = v0;
            *reinterpret_cast<float2*>(C + (size_t)(row0 + 8) * M + col) = v1;
        }
    }
#undef LOAD_CHUNK
}

// ---------------- fused weight split (fp16 hi/lo, all 4 weights) -------------
#define WSZ (G3*Hq)          // 786432
#define SPLIT_TOTAL (3*WSZ + MH*Hq)
__global__ void split_all(const float* __restrict__ Whh0, const float* __restrict__ Wih1,
                          const float* __restrict__ Whh1, const float* __restrict__ W1)
{
    int idx = blockIdx.x * blockDim.x + threadIdx.x;
    if (idx >= SPLIT_TOTAL) return;
    const float* src; __half* hi; __half* lo; int i;
    if (idx < WSZ)            { src = Whh0; hi = g_Whh0hi; lo = g_Whh0lo; i = idx; }
    else if (idx < 2*WSZ)     { src = Wih1; hi = g_Wih1hi; lo = g_Wih1lo; i = idx - WSZ; }
    else if (idx < 3*WSZ)     { src = Whh1; hi = g_Whh1hi; lo = g_Whh1lo; i = idx - 2*WSZ; }
    else                      { src = W1;   hi = g_W1hi;   lo = g_W1lo;   i = idx - 3*WSZ; }
    float v = src[i];
    __half h = __float2half_rn(v);
    hi[i] = h;
    lo[i] = __float2half_rn(v - __half2float(h));
}

// ---------------- init -------------------------------------------------------
// hidden row i = a*B + b holds social[b][a]
__global__ void init_kernel(const float* __restrict__ social,
                            const float* __restrict__ lastpos)
{
    int idx = blockIdx.x * blockDim.x + threadIdx.x;
    if (idx < Nq * Hq) {
        int i = idx >> 9;
        int cch = idx & (Hq - 1);
        int b = i & (Bq - 1);
        int a = i >> 6;
        float v = social[(b * Aq + a) * Hq + cch];
        g_h0[idx] = v;
        g_h1[idx] = v;
        __half h = __float2half_rn(v);
        g_h0h[idx] = h;
        g_h1h[idx] = h;
    }
    if (idx < Nq * Oq) g_x[idx] = lastpos[idx];
}

// ---------------- GRU combine layer 0 (vectorized x4, inline x@Wih0) ---------
__global__ __launch_bounds__(256, 3) void combine0(
                         const float* __restrict__ gh,
                         float* __restrict__ h,
                         __half* __restrict__ hh,
                         const float* __restrict__ Wih0,
                         const float* __restrict__ bih,
                         const float* __restrict__ bhh)
{
    int v4 = blockIdx.x * blockDim.x + threadIdx.x;   // Nq*Hq/4 threads
    if (v4 >= Nq * Hq / 4) return;
    int idx = v4 * 4;
    int i = idx >> 9;
    int j = idx & (Hq - 1);

    float x0 = g_x[i * 2 + 0];
    float x1 = g_x[i * 2 + 1];

    const float* g = gh + (size_t)i * G3;
    float4 gr = *(const float4*)(g + 0 * Hq + j);
    float4 gz = *(const float4*)(g + 1 * Hq + j);
    float4 gn = *(const float4*)(g + 2 * Hq + j);
    float4 br_i = *(const float4*)(bih + 0 * Hq + j);
    float4 bz_i = *(const float4*)(bih + 1 * Hq + j);
    float4 bn_i = *(const float4*)(bih + 2 * Hq + j);
    float4 br_h = *(const float4*)(bhh + 0 * Hq + j);
    float4 bz_h = *(const float4*)(bhh + 1 * Hq + j);
    float4 bn_h = *(const float4*)(bhh + 2 * Hq + j);
    float4 hp = *(const float4*)(h + idx);

    float4 wr0 = *(const float4*)(Wih0 + (0 * Hq + j) * 2);
    float4 wr1 = *(const float4*)(Wih0 + (0 * Hq + j) * 2 + 4);
    float4 wz0 = *(const float4*)(Wih0 + (1 * Hq + j) * 2);
    float4 wz1 = *(const float4*)(Wih0 + (1 * Hq + j) * 2 + 4);
    float4 wn0 = *(const float4*)(Wih0 + (2 * Hq + j) * 2);
    float4 wn1 = *(const float4*)(Wih0 + (2 * Hq + j) * 2 + 4);

    float ho[4]; __half hhv[4];
#pragma unroll
    for (int u = 0; u < 4; u++) {
        float wir0 = (u < 2) ? ((u == 0) ? wr0.x : wr0.z) : ((u == 2) ? wr1.x : wr1.z);
        float wir1 = (u < 2) ? ((u == 0) ? wr0.y : wr0.w) : ((u == 2) ? wr1.y : wr1.w);
        float wiz0 = (u < 2) ? ((u == 0) ? wz0.x : wz0.z) : ((u == 2) ? wz1.x : wz1.z);
        float wiz1 = (u < 2) ? ((u == 0) ? wz0.y : wz0.w) : ((u == 2) ? wz1.y : wz1.w);
        float win0 = (u < 2) ? ((u == 0) ? wn0.x : wn0.z) : ((u == 2) ? wn1.x : wn1.z);
        float win1 = (u < 2) ? ((u == 0) ? wn0.y : wn0.w) : ((u == 2) ? wn1.y : wn1.w);

        float grv = (&gr.x)[u], gzv = (&gz.x)[u], gnv = (&gn.x)[u];
        float ir  = x0 * wir0 + x1 * wir1 + (&br_i.x)[u];
        float iz  = x0 * wiz0 + x1 * wiz1 + (&bz_i.x)[u];
        float in_ = x0 * win0 + x1 * win1 + (&bn_i.x)[u];
        float hr = grv + (&br_h.x)[u];
        float hz = gzv + (&bz_h.x)[u];
        float hn = gnv + (&bn_h.x)[u];

        float r = 1.0f / (1.0f + expf(-(ir + hr)));
        float z = 1.0f / (1.0f + expf(-(iz + hz)));
        float n = tanhf(in_ + r * hn);
        float v = (1.0f - z) * n + z * (&hp.x)[u];
        ho[u] = v;
        hhv[u] = __float2half_rn(v);
    }
    *(float4*)(h + idx) = make_float4(ho[0], ho[1], ho[2], ho[3]);
    *(uint2*)(hh + idx) = *(uint2*)hhv;
}

// ---------------- GRU combine layer 1 (vectorized x4) ------------------------
__global__ __launch_bounds__(256, 3) void combine1(
                         const float* __restrict__ gi,
                         const float* __restrict__ gh,
                         float* __restrict__ h,
                         __half* __restrict__ hh,
                         const float* __restrict__ bih,
                         const float* __restrict__ bhh)
{
    int v4 = blockIdx.x * blockDim.x + threadIdx.x;
    if (v4 >= Nq * Hq / 4) return;
    int idx = v4 * 4;
    int i = idx >> 9;
    int j = idx & (Hq - 1);

    const float* a = gi + (size_t)i * G3;
    const float* g = gh + (size_t)i * G3;

    float4 ar = *(const float4*)(a + 0 * Hq + j);
    float4 az = *(const float4*)(a + 1 * Hq + j);
    float4 an = *(const float4*)(a + 2 * Hq + j);
    float4 gr = *(const float4*)(g + 0 * Hq + j);
    float4 gz = *(const float4*)(g + 1 * Hq + j);
    float4 gn = *(const float4*)(g + 2 * Hq + j);
    float4 br_i = *(const float4*)(bih + 0 * Hq + j);
    float4 bz_i = *(const float4*)(bih + 1 * Hq + j);
    float4 bn_i = *(const float4*)(bih + 2 * Hq + j);
    float4 br_h = *(const float4*)(bhh + 0 * Hq + j);
    float4 bz_h = *(const float4*)(bhh + 1 * Hq + j);
    float4 bn_h = *(const float4*)(bhh + 2 * Hq + j);
    float4 hp = *(const float4*)(h + idx);

    float ho[4]; __half hhv[4];
#pragma unroll
    for (int u = 0; u < 4; u++) {
        float ir  = (&ar.x)[u] + (&br_i.x)[u];
        float iz  = (&az.x)[u] + (&bz_i.x)[u];
        float in_ = (&an.x)[u] + (&bn_i.x)[u];
        float hr  = (&gr.x)[u] + (&br_h.x)[u];
        float hz  = (&gz.x)[u] + (&bz_h.x)[u];
        float hn  = (&gn.x)[u] + (&bn_h.x)[u];

        float r = 1.0f / (1.0f + expf(-(ir + hr)));
        float z = 1.0f / (1.0f + expf(-(iz + hz)));
        float n = tanhf(in_ + r * hn);
        float v = (1.0f - z) * n + z * (&hp.x)[u];
        ho[u] = v;
        hhv[u] = __float2half_rn(v);
    }
    *(float4*)(h + idx) = make_float4(ho[0], ho[1], ho[2], ho[3]);
    *(uint2*)(hh + idx) = *(uint2*)hhv;
}

// ---------------- prediction: pred = Mh @ W2^T + b2 --------------------------
__global__ void pred_kernel(const float* __restrict__ Mh,
                            const float* __restrict__ W2,
                            const float* __restrict__ b2,
                            float* __restrict__ out, int t)
{
    int gwarp = (blockIdx.x * blockDim.x + threadIdx.x) >> 5;
    int lane  = threadIdx.x & 31;
    if (gwarp >= Nq) return;

    const float* mrow = Mh + (size_t)gwarp * MH;
    float s0 = 0.0f, s1 = 0.0f;
#pragma unroll
    for (int u = 0; u < 8; u++) {
        float m = mrow[lane + 32 * u];
        s0 = fmaf(m, W2[      lane + 32 * u], s0);
        s1 = fmaf(m, W2[MH +  lane + 32 * u], s1);
    }
#pragma unroll
    for (int off = 16; off; off >>= 1) {
        s0 += __shfl_xor_sync(0xFFFFFFFFu, s0, off);
        s1 += __shfl_xor_sync(0xFFFFFFFFu, s1, off);
    }
    if (lane == 0) {
        s0 += b2[0];
        s1 += b2[1];
        g_x[gwarp * 2 + 0] = s0;
        g_x[gwarp * 2 + 1] = s1;
        int b = gwarp >> 8;
        int a = gwarp & (Aq - 1);
        float* o = out + (((size_t)b * Tq + t) * Aq + a) * Oq;
        o[0] = s0;
        o[1] = s1;
    }
}

// ---------------- launch -----------------------------------------------------
extern "C" void kernel_launch(void* const* d_in, const int* in_sizes, int n_in,
                              void* d_out, int out_size)
{
    const float* social  = (const float*)d_in[0];
    const float* lastpos = (const float*)d_in[1];
    const float* Wih0    = (const float*)d_in[2];
    const float* Whh0    = (const float*)d_in[3];
    const float* bih0    = (const float*)d_in[4];
    const float* bhh0    = (const float*)d_in[5];
    const float* Wih1    = (const float*)d_in[6];
    const float* Whh1    = (const float*)d_in[7];
    const float* bih1    = (const float*)d_in[8];
    const float* bhh1    = (const float*)d_in[9];
    const float* W1      = (const float*)d_in[10];
    const float* b1      = (const float*)d_in[11];
    const float* W2      = (const float*)d_in[12];
    const float* b2      = (const float*)d_in[13];
    float* out = (float*)d_out;

    float *h0, *h1, *gate0, *gate1, *mbuf;
    __half *h0h, *h1h;
    __half *whh0hi, *whh0lo, *wih1hi, *wih1lo, *whh1hi, *whh1lo, *w1hi, *w1lo;
    cudaGetSymbolAddress((void**)&h0,    g_h0);
    cudaGetSymbolAddress((void**)&h1,    g_h1);
    cudaGetSymbolAddress((void**)&gate0, g_gate0);
    cudaGetSymbolAddress((void**)&gate1, g_gate1);
    cudaGetSymbolAddress((void**)&mbuf,  g_m);
    cudaGetSymbolAddress((void**)&h0h,   g_h0h);
    cudaGetSymbolAddress((void**)&h1h,   g_h1h);
    cudaGetSymbolAddress((void**)&whh0hi, g_Whh0hi);
    cudaGetSymbolAddress((void**)&whh0lo, g_Whh0lo);
    cudaGetSymbolAddress((void**)&wih1hi, g_Wih1hi);
    cudaGetSymbolAddress((void**)&wih1lo, g_Wih1lo);
    cudaGetSymbolAddress((void**)&whh1hi, g_Whh1hi);
    cudaGetSymbolAddress((void**)&whh1lo, g_Whh1lo);
    cudaGetSymbolAddress((void**)&w1hi,  g_W1hi);
    cudaGetSymbolAddress((void**)&w1lo,  g_W1lo);

    cudaFuncSetAttribute(gemm_mma, cudaFuncAttributeMaxDynamicSharedMemorySize, GEMM_SMEM);

    // split weights (fused, idempotent, every call)
    split_all<<<(SPLIT_TOTAL + 255) / 256, 256>>>(Whh0, Wih1, Whh1, W1);

    init_kernel<<<(Nq * Hq + 255) / 256, 256>>>(social, lastpos);

    // GEMM problem descriptors
    GemmProb pGh0; pGh0.segs.a[0] = h0h; pGh0.segs.a[1] = h0h;
                   pGh0.segs.w[0] = whh0hi; pGh0.segs.w[1] = whh0lo;
                   pGh0.C = gate0; pGh0.M = G3; pGh0.bias = nullptr; pGh0.relu = 0;
    GemmProb pGh1; pGh1.segs.a[0] = h1h; pGh1.segs.a[1] = h1h;
                   pGh1.segs.w[0] = whh1hi; pGh1.segs.w[1] = whh1lo;
                   pGh1.C = gate1; pGh1.M = G3; pGh1.bias = nullptr; pGh1.relu = 0;
    GemmProb pGi1; pGi1.segs.a[0] = h0h; pGi1.segs.a[1] = h0h;
                   pGi1.segs.w[0] = wih1hi; pGi1.segs.w[1] = wih1lo;
                   pGi1.C = gate0; pGi1.M = G3; pGi1.bias = nullptr; pGi1.relu = 0;
    GemmProb pMlp; pMlp.segs.a[0] = h1h; pMlp.segs.a[1] = h1h;
                   pMlp.segs.w[0] = w1hi; pMlp.segs.w[1] = w1lo;
                   pMlp.C = mbuf; pMlp.M = MH; pMlp.bias = b1; pMlp.relu = 1;

    dim3 gridDual(G3 / BN, Nq / BM, 2);   // 12 x 128 x 2
    dim3 gridSingle(G3 / BN, Nq / BM, 1); // 12 x 128
    dim3 gridMlp(MH / BN, Nq / BM, 1);    // 2 x 128
    int combBlocks = (Nq * Hq / 4 + 255) / 256;

    for (int t = 0; t < Tq; t++) {
        // merged: Gh0 = h0 @ Whh0^T  and  Gh1 = h1 @ Whh1^T  (independent)
        gemm_mma<<<gridDual, 256, GEMM_SMEM>>>(pGh0, pGh1, pGh1);
        combine0<<<combBlocks, 256>>>(gate0, h0, h0h, Wih0, bih0, bhh0);

        // Gi1 = h0n @ Wih1^T
        gemm_mma<<<gridSingle, 256, GEMM_SMEM>>>(pGi1, pGi1, pGi1);
        combine1<<<combBlocks, 256>>>(gate0, gate1, h1, h1h, bih1, bhh1);

        // MLP hidden: m = relu(h1 @ W1^T + b1)
        gemm_mma<<<gridMlp, 256, GEMM_SMEM>>>(pMlp, pMlp, pMlp);
        pred_kernel<<<Nq * 32 / 256, 256>>>(mbuf, W2, b2, out, t);
    }
}

// round 15
// speedup vs baseline: 1.0376x; 1.0271x over previous
#include <cuda_runtime.h>
#include <cuda_fp16.h>
#include <math.h>
#include <stdint.h>

// Problem constants
#define Bq 64
#define Aq 256
#define Hq 512
#define Oq 2
#define Tq 32
#define Nq (Bq*Aq)     // 16384 rows
#define G3 (3*Hq)      // 1536
#define MH (Hq/2)      // 256

// ---------------- device globals (no allocation allowed) --------------------
__device__ float g_h0[Nq*Hq];
__device__ float g_h1[Nq*Hq];
__device__ __half g_h0h[Nq*Hq];    // fp16 copy of h0
__device__ __half g_h1h[Nq*Hq];    // fp16 copy of h1
__device__ float g_gate0[Nq*G3];
__device__ float g_gate1[Nq*G3];
__device__ float g_x[Nq*Oq];
__device__ __half g_Whh0hi[G3*Hq], g_Whh0lo[G3*Hq];
__device__ __half g_Wih1hi[G3*Hq], g_Wih1lo[G3*Hq];
__device__ __half g_Whh1hi[G3*Hq], g_Whh1lo[G3*Hq];
__device__ __half g_W1hi[MH*Hq],  g_W1lo[MH*Hq];

// ---------------- helpers ----------------------------------------------------
__device__ __forceinline__ uint32_t smem_u32(const void* p) {
    uint32_t a;
    asm("{ .reg .u64 t; cvta.to.shared.u64 t, %1; cvt.u32.u64 %0, t; }" : "=r"(a) : "l"(p));
    return a;
}
__device__ __forceinline__ void cp_async16(uint32_t dst, const void* src) {
    asm volatile("cp.async.cg.shared.global [%0], [%1], 16;" :: "r"(dst), "l"(src) : "memory");
}
__device__ __forceinline__ void ldmatrix_x4(uint32_t& r0, uint32_t& r1, uint32_t& r2, uint32_t& r3, uint32_t addr) {
    asm volatile("ldmatrix.sync.aligned.m8n8.x4.shared.b16 {%0,%1,%2,%3}, [%4];"
                 : "=r"(r0), "=r"(r1), "=r"(r2), "=r"(r3) : "r"(addr));
}
__device__ __forceinline__ void mma16816(float* d, uint32_t a0, uint32_t a1, uint32_t a2, uint32_t a3,
                                         uint32_t b0, uint32_t b1) {
    asm volatile("mma.sync.aligned.m16n8k16.row.col.f32.f16.f16.f32 "
                 "{%0,%1,%2,%3}, {%4,%5,%6,%7}, {%8,%9}, {%0,%1,%2,%3};"
                 : "+f"(d[0]), "+f"(d[1]), "+f"(d[2]), "+f"(d[3])
                 : "r"(a0), "r"(a1), "r"(a2), "r"(a3), "r"(b0), "r"(b1));
}

// ---------------- gate GEMM (mma.sync fp16, 2-pass hi/lo weight split) -------
// C[Nq x M] = A[Nq x 512] @ (Whi + Wlo)[M x 512]^T   with A = fp16(act)
// tile 128x128, 8 warps as 4 row-groups x 2 col-groups (32x64 warp tile),
// K chunks of 64 halves, 3-stage cp.async pipeline with a single
// __syncthreads per chunk, 2 CTAs/SM. blockIdx.z selects one of 2 problems.
#define BM 128
#define BN 128
#define BKH 64                      // halves per chunk
#define ROWB 144                    // smem row stride bytes (72 halves, padded)
#define STAGE_BYTES ((BM + BN) * ROWB)   // 36864
#define NSTAGE 3
#define GEMM_SMEM (NSTAGE * STAGE_BYTES) // 110592
#define NSEG 2
#define NCH (NSEG * 8)              // 16 chunks

struct GemmSegs {
    const __half* a[NSEG];
    const __half* w[NSEG];
};
struct GemmProb {
    GemmSegs segs;
    float* C;
};

__global__ __launch_bounds__(256, 2) void gemm_mma(GemmProb p0, GemmProb p1)
{
    extern __shared__ char sm[];
    const GemmProb& p = blockIdx.z ? p1 : p0;

    const int tid  = threadIdx.x;
    const int warp = tid >> 5;
    const int lane = tid & 31;
    const int rowBase = blockIdx.y * BM;
    const int colBase = blockIdx.x * BN;
    const int wr = (warp & 3) * 32;      // warp row offset (0/32/64/96)
    const int wc = (warp >> 2) * 64;     // warp col offset (0/64)

    const GemmSegs& segs = p.segs;
    float* __restrict__ C = p.C;

    const uint32_t sbase = smem_u32(sm);

    float acc[2][8][4];
#pragma unroll
    for (int i = 0; i < 2; i++)
#pragma unroll
        for (int j = 0; j < 8; j++)
#pragma unroll
            for (int v = 0; v < 4; v++) acc[i][j][v] = 0.0f;

#define LOAD_CHUNK(c, s) do { \
        int _seg  = (c) >> 3; \
        int _koff = ((c) & 7) * BKH; \
        const __half* _Ag = segs.a[_seg] + (size_t)rowBase * Hq + _koff; \
        const __half* _Wg = segs.w[_seg] + (size_t)colBase * Hq + _koff; \
        uint32_t _ab = sbase + (s) * STAGE_BYTES; \
        uint32_t _wb = _ab + BM * ROWB; \
        _Pragma("unroll") \
        for (int _i = 0; _i < 4; _i++) { \
            int _lin = tid + _i * 256; \
            int _r = _lin >> 3, _sg = _lin & 7; \
            cp_async16(_ab + _r * ROWB + _sg * 16, _Ag + (size_t)_r * Hq + _sg * 8); \
            cp_async16(_wb + _r * ROWB + _sg * 16, _Wg + (size_t)_r * Hq + _sg * 8); \
        } \
        asm volatile("cp.async.commit_group;" ::: "memory"); \
    } while (0)

    LOAD_CHUNK(0, 0);
    LOAD_CHUNK(1, 1);

    const uint32_t aAddrBase = (wr + (lane & 15)) * ROWB + (lane >> 4) * 16;
    const uint32_t wAddrBase = BM * ROWB
        + (wc + (lane & 7) + ((lane >> 4) & 1) * 8) * ROWB
        + ((lane >> 3) & 1) * 16;

    for (int c = 0; c < NCH; c++) {
        if (c + 1 < NCH) {
            asm volatile("cp.async.wait_group 1;" ::: "memory");
        } else {
            asm volatile("cp.async.wait_group 0;" ::: "memory");
        }
        __syncthreads();

        if (c + 2 < NCH) LOAD_CHUNK(c + 2, (c + 2) % NSTAGE);

        const uint32_t stageOff = sbase + (c % NSTAGE) * STAGE_BYTES;
#pragma unroll
        for (int ks = 0; ks < 4; ks++) {
            uint32_t af[2][4], bf[4][4];
#pragma unroll
            for (int rt = 0; rt < 2; rt++)
                ldmatrix_x4(af[rt][0], af[rt][1], af[rt][2], af[rt][3],
                            stageOff + aAddrBase + rt * 16 * ROWB + ks * 32);
#pragma unroll
            for (int cp = 0; cp < 4; cp++)
                ldmatrix_x4(bf[cp][0], bf[cp][1], bf[cp][2], bf[cp][3],
                            stageOff + wAddrBase + cp * 16 * ROWB + ks * 32);
#pragma unroll
            for (int rt = 0; rt < 2; rt++)
#pragma unroll
                for (int ct = 0; ct < 8; ct++) {
                    int cp = ct >> 1, hf = (ct & 1) * 2;
                    mma16816(acc[rt][ct], af[rt][0], af[rt][1], af[rt][2], af[rt][3],
                             bf[cp][hf], bf[cp][hf + 1]);
                }
        }
    }

    const int gid = lane >> 2;
    const int tig = lane & 3;
#pragma unroll
    for (int rt = 0; rt < 2; rt++) {
        int row0 = rowBase + wr + rt * 16 + gid;
#pragma unroll
        for (int ct = 0; ct < 8; ct++) {
            int col = colBase + wc + ct * 8 + tig * 2;
            float2 v0 = make_float2(acc[rt][ct][0], acc[rt][ct][1]);
            float2 v1 = make_float2(acc[rt][ct][2], acc[rt][ct][3]);
            *reinterpret_cast<float2*>(C + (size_t)row0 * G3 + col) = v0;
            *reinterpret_cast<float2*>(C + (size_t)(row0 + 8) * G3 + col) = v1;
        }
    }
#undef LOAD_CHUNK
}

// ---------------- fused MLP + prediction kernel ------------------------------
// Per CTA: 128 rows x ALL 256 MLP cols. m = relu(h1@W1^T + b1) held in regs,
// then pred = m @ W2^T + b2 reduced in-CTA; writes g_x and out directly.
// 8 warps = 4 row-groups x 2 col-groups; warp tile 32 x 128.
// grid = 128 CTAs (one wave, <=1 CTA/SM).
#define MP_STAGE ((BM + MH) * ROWB)       // (128+256)*144 = 55296
#define MP_SMEM  (NSTAGE * MP_STAGE)      // 165888

__global__ __launch_bounds__(256, 1) void mlp_pred(
    const __half* __restrict__ Ain,   // h1h
    const __half* __restrict__ Whi,   // W1 hi
    const __half* __restrict__ Wlo,   // W1 lo
    const float* __restrict__ b1,
    const float* __restrict__ W2,     // [2][256]
    const float* __restrict__ b2,
    float* __restrict__ out, int t)
{
    extern __shared__ char sm[];
    __shared__ float sred[2][BM][2];  // [s0/s1][local row][col group]

    const int tid  = threadIdx.x;
    const int warp = tid >> 5;
    const int lane = tid & 31;
    const int rowBase = blockIdx.x * BM;
    const int wr = (warp & 3) * 32;       // row group (0/32/64/96)
    const int wc = (warp >> 2) * 128;     // col group (0/128)
    const int cg = warp >> 2;

    const uint32_t sbase = smem_u32(sm);

    float acc[2][16][4];
#pragma unroll
    for (int i = 0; i < 2; i++)
#pragma unroll
        for (int j = 0; j < 16; j++)
#pragma unroll
            for (int v = 0; v < 4; v++) acc[i][j][v] = 0.0f;

    // chunk loader: A 128 rows (4 iters) + W 256 rows (8 iters)
#define MP_LOAD(c, s) do { \
        int _koff = ((c) & 7) * BKH; \
        const __half* _Ag = Ain + (size_t)rowBase * Hq + _koff; \
        const __half* _Wg = (((c) >> 3) ? Wlo : Whi) + _koff; \
        uint32_t _ab = sbase + (s) * MP_STAGE; \
        uint32_t _wb = _ab + BM * ROWB; \
        _Pragma("unroll") \
        for (int _i = 0; _i < 4; _i++) { \
            int _lin = tid + _i * 256; \
            int _r = _lin >> 3, _sg = _lin & 7; \
            cp_async16(_ab + _r * ROWB + _sg * 16, _Ag + (size_t)_r * Hq + _sg * 8); \
        } \
        _Pragma("unroll") \
        for (int _i = 0; _i < 8; _i++) { \
            int _lin = tid + _i * 256; \
            int _r = _lin >> 3, _sg = _lin & 7; \
            cp_async16(_wb + _r * ROWB + _sg * 16, _Wg + (size_t)_r * Hq + _sg * 8); \
        } \
        asm volatile("cp.async.commit_group;" ::: "memory"); \
    } while (0)

    MP_LOAD(0, 0);
    MP_LOAD(1, 1);

    const uint32_t aAddrBase = (wr + (lane & 15)) * ROWB + (lane >> 4) * 16;
    const uint32_t wAddrBase = BM * ROWB
        + (wc + (lane & 7) + ((lane >> 4) & 1) * 8) * ROWB
        + ((lane >> 3) & 1) * 16;

    for (int c = 0; c < NCH; c++) {
        if (c + 1 < NCH) {
            asm volatile("cp.async.wait_group 1;" ::: "memory");
        } else {
            asm volatile("cp.async.wait_group 0;" ::: "memory");
        }
        __syncthreads();

        if (c + 2 < NCH) MP_LOAD(c + 2, (c + 2) % NSTAGE);

        const uint32_t stageOff = sbase + (c % NSTAGE) * MP_STAGE;
#pragma unroll
        for (int ks = 0; ks < 4; ks++) {
            uint32_t af[2][4], bf[8][4];
#pragma unroll
            for (int rt = 0; rt < 2; rt++)
                ldmatrix_x4(af[rt][0], af[rt][1], af[rt][2], af[rt][3],
                            stageOff + aAddrBase + rt * 16 * ROWB + ks * 32);
#pragma unroll
            for (int cp = 0; cp < 8; cp++)
                ldmatrix_x4(bf[cp][0], bf[cp][1], bf[cp][2], bf[cp][3],
                            stageOff + wAddrBase + cp * 16 * ROWB + ks * 32);
#pragma unroll
            for (int rt = 0; rt < 2; rt++)
#pragma unroll
                for (int ct = 0; ct < 16; ct++) {
                    int cp = ct >> 1, hf = (ct & 1) * 2;
                    mma16816(acc[rt][ct], af[rt][0], af[rt][1], af[rt][2], af[rt][3],
                             bf[cp][hf], bf[cp][hf + 1]);
                }
        }
    }
#undef MP_LOAD

    // ---- fused pred epilogue: s = relu(acc + b1) @ W2^T --------------------
    const int gid = lane >> 2;
    const int tig = lane & 3;
    float s[2][4];                     // [pred dim][rt*2 + h]
#pragma unroll
    for (int d = 0; d < 2; d++)
#pragma unroll
        for (int k = 0; k < 4; k++) s[d][k] = 0.0f;

#pragma unroll
    for (int rt = 0; rt < 2; rt++)
#pragma unroll
        for (int ct = 0; ct < 16; ct++) {
            int col = wc + ct * 8 + tig * 2;
            float b1a = b1[col], b1b = b1[col + 1];
            float w0a = W2[col],        w0b = W2[col + 1];
            float w1a = W2[MH + col],   w1b = W2[MH + col + 1];
            float m0 = fmaxf(acc[rt][ct][0] + b1a, 0.f);
            float m1 = fmaxf(acc[rt][ct][1] + b1b, 0.f);
            float m2 = fmaxf(acc[rt][ct][2] + b1a, 0.f);
            float m3 = fmaxf(acc[rt][ct][3] + b1b, 0.f);
            s[0][rt * 2 + 0] += m0 * w0a + m1 * w0b;
            s[1][rt * 2 + 0] += m0 * w1a + m1 * w1b;
            s[0][rt * 2 + 1] += m2 * w0a + m3 * w0b;
            s[1][rt * 2 + 1] += m2 * w1a + m3 * w1b;
        }

    // reduce across the 4 lanes of each row group (tig axis)
#pragma unroll
    for (int off = 1; off <= 2; off <<= 1)
#pragma unroll
        for (int d = 0; d < 2; d++)
#pragma unroll
            for (int k = 0; k < 4; k++)
                s[d][k] += __shfl_xor_sync(0xFFFFFFFFu, s[d][k], off);

    if (tig == 0) {
#pragma unroll
        for (int rt = 0; rt < 2; rt++)
#pragma unroll
            for (int h = 0; h < 2; h++) {
                int row = wr + rt * 16 + gid + h * 8;
                sred[0][row][cg] = s[0][rt * 2 + h];
                sred[1][row][cg] = s[1][rt * 2 + h];
            }
    }
    __syncthreads();

    if (tid < BM) {
        int row = tid;
        float r0 = sred[0][row][0] + sred[0][row][1] + b2[0];
        float r1 = sred[1][row][0] + sred[1][row][1] + b2[1];
        int grow = rowBase + row;
        g_x[grow * 2 + 0] = r0;
        g_x[grow * 2 + 1] = r1;
        int b = grow >> 8;
        int a = grow & (Aq - 1);
        float* o = out + (((size_t)b * Tq + t) * Aq + a) * Oq;
        o[0] = r0;
        o[1] = r1;
    }
}

// ---------------- fused weight split (fp16 hi/lo, all 4 weights) -------------
#define WSZ (G3*Hq)          // 786432
#define SPLIT_TOTAL (3*WSZ + MH*Hq)
__global__ void split_all(const float* __restrict__ Whh0, const float* __restrict__ Wih1,
                          const float* __restrict__ Whh1, const float* __restrict__ W1)
{
    int idx = blockIdx.x * blockDim.x + threadIdx.x;
    if (idx >= SPLIT_TOTAL) return;
    const float* src; __half* hi; __half* lo; int i;
    if (idx < WSZ)            { src = Whh0; hi = g_Whh0hi; lo = g_Whh0lo; i = idx; }
    else if (idx < 2*WSZ)     { src = Wih1; hi = g_Wih1hi; lo = g_Wih1lo; i = idx - WSZ; }
    else if (idx < 3*WSZ)     { src = Whh1; hi = g_Whh1hi; lo = g_Whh1lo; i = idx - 2*WSZ; }
    else                      { src = W1;   hi = g_W1hi;   lo = g_W1lo;   i = idx - 3*WSZ; }
    float v = src[i];
    __half h = __float2half_rn(v);
    hi[i] = h;
    lo[i] = __float2half_rn(v - __half2float(h));
}

// ---------------- init -------------------------------------------------------
// hidden row i = a*B + b holds social[b][a]
__global__ void init_kernel(const float* __restrict__ social,
                            const float* __restrict__ lastpos)
{
    int idx = blockIdx.x * blockDim.x + threadIdx.x;
    if (idx < Nq * Hq) {
        int i = idx >> 9;
        int cch = idx & (Hq - 1);
        int b = i & (Bq - 1);
        int a = i >> 6;
        float v = social[(b * Aq + a) * Hq + cch];
        g_h0[idx] = v;
        g_h1[idx] = v;
        __half h = __float2half_rn(v);
        g_h0h[idx] = h;
        g_h1h[idx] = h;
    }
    if (idx < Nq * Oq) g_x[idx] = lastpos[idx];
}

// ---------------- GRU combine layer 0 (vectorized x4, inline x@Wih0) ---------
__global__ __launch_bounds__(256, 3) void combine0(
                         const float* __restrict__ gh,
                         float* __restrict__ h,
                         __half* __restrict__ hh,
                         const float* __restrict__ Wih0,
                         const float* __restrict__ bih,
                         const float* __restrict__ bhh)
{
    int v4 = blockIdx.x * blockDim.x + threadIdx.x;
    if (v4 >= Nq * Hq / 4) return;
    int idx = v4 * 4;
    int i = idx >> 9;
    int j = idx & (Hq - 1);

    float x0 = g_x[i * 2 + 0];
    float x1 = g_x[i * 2 + 1];

    const float* g = gh + (size_t)i * G3;
    float4 gr = *(const float4*)(g + 0 * Hq + j);
    float4 gz = *(const float4*)(g + 1 * Hq + j);
    float4 gn = *(const float4*)(g + 2 * Hq + j);
    float4 br_i = *(const float4*)(bih + 0 * Hq + j);
    float4 bz_i = *(const float4*)(bih + 1 * Hq + j);
    float4 bn_i = *(const float4*)(bih + 2 * Hq + j);
    float4 br_h = *(const float4*)(bhh + 0 * Hq + j);
    float4 bz_h = *(const float4*)(bhh + 1 * Hq + j);
    float4 bn_h = *(const float4*)(bhh + 2 * Hq + j);
    float4 hp = *(const float4*)(h + idx);

    float4 wr0 = *(const float4*)(Wih0 + (0 * Hq + j) * 2);
    float4 wr1 = *(const float4*)(Wih0 + (0 * Hq + j) * 2 + 4);
    float4 wz0 = *(const float4*)(Wih0 + (1 * Hq + j) * 2);
    float4 wz1 = *(const float4*)(Wih0 + (1 * Hq + j) * 2 + 4);
    float4 wn0 = *(const float4*)(Wih0 + (2 * Hq + j) * 2);
    float4 wn1 = *(const float4*)(Wih0 + (2 * Hq + j) * 2 + 4);

    float ho[4]; __half hhv[4];
#pragma unroll
    for (int u = 0; u < 4; u++) {
        float wir0 = (u < 2) ? ((u == 0) ? wr0.x : wr0.z) : ((u == 2) ? wr1.x : wr1.z);
        float wir1 = (u < 2) ? ((u == 0) ? wr0.y : wr0.w) : ((u == 2) ? wr1.y : wr1.w);
        float wiz0 = (u < 2) ? ((u == 0) ? wz0.x : wz0.z) : ((u == 2) ? wz1.x : wz1.z);
        float wiz1 = (u < 2) ? ((u == 0) ? wz0.y : wz0.w) : ((u == 2) ? wz1.y : wz1.w);
        float win0 = (u < 2) ? ((u == 0) ? wn0.x : wn0.z) : ((u == 2) ? wn1.x : wn1.z);
        float win1 = (u < 2) ? ((u == 0) ? wn0.y : wn0.w) : ((u == 2) ? wn1.y : wn1.w);

        float grv = (&gr.x)[u], gzv = (&gz.x)[u], gnv = (&gn.x)[u];
        float ir  = x0 * wir0 + x1 * wir1 + (&br_i.x)[u];
        float iz  = x0 * wiz0 + x1 * wiz1 + (&bz_i.x)[u];
        float in_ = x0 * win0 + x1 * win1 + (&bn_i.x)[u];
        float hr = grv + (&br_h.x)[u];
        float hz = gzv + (&bz_h.x)[u];
        float hn = gnv + (&bn_h.x)[u];

        float r = 1.0f / (1.0f + expf(-(ir + hr)));
        float z = 1.0f / (1.0f + expf(-(iz + hz)));
        float n = tanhf(in_ + r * hn);
        float v = (1.0f - z) * n + z * (&hp.x)[u];
        ho[u] = v;
        hhv[u] = __float2half_rn(v);
    }
    *(float4*)(h + idx) = make_float4(ho[0], ho[1], ho[2], ho[3]);
    *(uint2*)(hh + idx) = *(uint2*)hhv;
}

// ---------------- GRU combine layer 1 (vectorized x4) ------------------------
__global__ __launch_bounds__(256, 3) void combine1(
                         const float* __restrict__ gi,
                         const float* __restrict__ gh,
                         float* __restrict__ h,
                         __half* __restrict__ hh,
                         const float* __restrict__ bih,
                         const float* __restrict__ bhh)
{
    int v4 = blockIdx.x * blockDim.x + threadIdx.x;
    if (v4 >= Nq * Hq / 4) return;
    int idx = v4 * 4;
    int i = idx >> 9;
    int j = idx & (Hq - 1);

    const float* a = gi + (size_t)i * G3;
    const float* g = gh + (size_t)i * G3;

    float4 ar = *(const float4*)(a + 0 * Hq + j);
    float4 az = *(const float4*)(a + 1 * Hq + j);
    float4 an = *(const float4*)(a + 2 * Hq + j);
    float4 gr = *(const float4*)(g + 0 * Hq + j);
    float4 gz = *(const float4*)(g + 1 * Hq + j);
    float4 gn = *(const float4*)(g + 2 * Hq + j);
    float4 br_i = *(const float4*)(bih + 0 * Hq + j);
    float4 bz_i = *(const float4*)(bih + 1 * Hq + j);
    float4 bn_i = *(const float4*)(bih + 2 * Hq + j);
    float4 br_h = *(const float4*)(bhh + 0 * Hq + j);
    float4 bz_h = *(const float4*)(bhh + 1 * Hq + j);
    float4 bn_h = *(const float4*)(bhh + 2 * Hq + j);
    float4 hp = *(const float4*)(h + idx);

    float ho[4]; __half hhv[4];
#pragma unroll
    for (int u = 0; u < 4; u++) {
        float ir  = (&ar.x)[u] + (&br_i.x)[u];
        float iz  = (&az.x)[u] + (&bz_i.x)[u];
        float in_ = (&an.x)[u] + (&bn_i.x)[u];
        float hr  = (&gr.x)[u] + (&br_h.x)[u];
        float hz  = (&gz.x)[u] + (&bz_h.x)[u];
        float hn  = (&gn.x)[u] + (&bn_h.x)[u];

        float r = 1.0f / (1.0f + expf(-(ir + hr)));
        float z = 1.0f / (1.0f + expf(-(iz + hz)));
        float n = tanhf(in_ + r * hn);
        float v = (1.0f - z) * n + z * (&hp.x)[u];
        ho[u] = v;
        hhv[u] = __float2half_rn(v);
    }
    *(float4*)(h + idx) = make_float4(ho[0], ho[1], ho[2], ho[3]);
    *(uint2*)(hh + idx) = *(uint2*)hhv;
}

// ---------------- launch -----------------------------------------------------
extern "C" void kernel_launch(void* const* d_in, const int* in_sizes, int n_in,
                              void* d_out, int out_size)
{
    const float* social  = (const float*)d_in[0];
    const float* lastpos = (const float*)d_in[1];
    const float* Wih0    = (const float*)d_in[2];
    const float* Whh0    = (const float*)d_in[3];
    const float* bih0    = (const float*)d_in[4];
    const float* bhh0    = (const float*)d_in[5];
    const float* Wih1    = (const float*)d_in[6];
    const float* Whh1    = (const float*)d_in[7];
    const float* bih1    = (const float*)d_in[8];
    const float* bhh1    = (const float*)d_in[9];
    const float* W1      = (const float*)d_in[10];
    const float* b1      = (const float*)d_in[11];
    const float* W2      = (const float*)d_in[12];
    const float* b2      = (const float*)d_in[13];
    float* out = (float*)d_out;

    float *h0, *h1, *gate0, *gate1;
    __half *h0h, *h1h;
    __half *whh0hi, *whh0lo, *wih1hi, *wih1lo, *whh1hi, *whh1lo, *w1hi, *w1lo;
    cudaGetSymbolAddress((void**)&h0,    g_h0);
    cudaGetSymbolAddress((void**)&h1,    g_h1);
    cudaGetSymbolAddress((void**)&gate0, g_gate0);
    cudaGetSymbolAddress((void**)&gate1, g_gate1);
    cudaGetSymbolAddress((void**)&h0h,   g_h0h);
    cudaGetSymbolAddress((void**)&h1h,   g_h1h);
    cudaGetSymbolAddress((void**)&whh0hi, g_Whh0hi);
    cudaGetSymbolAddress((void**)&whh0lo, g_Whh0lo);
    cudaGetSymbolAddress((void**)&wih1hi, g_Wih1hi);
    cudaGetSymbolAddress((void**)&wih1lo, g_Wih1lo);
    cudaGetSymbolAddress((void**)&whh1hi, g_Whh1hi);
    cudaGetSymbolAddress((void**)&whh1lo, g_Whh1lo);
    cudaGetSymbolAddress((void**)&w1hi,  g_W1hi);
    cudaGetSymbolAddress((void**)&w1lo,  g_W1lo);

    cudaFuncSetAttribute(gemm_mma, cudaFuncAttributeMaxDynamicSharedMemorySize, GEMM_SMEM);
    cudaFuncSetAttribute(mlp_pred, cudaFuncAttributeMaxDynamicSharedMemorySize, MP_SMEM);

    // split weights (fused, idempotent, every call)
    split_all<<<(SPLIT_TOTAL + 255) / 256, 256>>>(Whh0, Wih1, Whh1, W1);

    init_kernel<<<(Nq * Hq + 255) / 256, 256>>>(social, lastpos);

    GemmProb pGh0; pGh0.segs.a[0] = h0h; pGh0.segs.a[1] = h0h;
                   pGh0.segs.w[0] = whh0hi; pGh0.segs.w[1] = whh0lo;
                   pGh0.C = gate0;
    GemmProb pGh1; pGh1.segs.a[0] = h1h; pGh1.segs.a[1] = h1h;
                   pGh1.segs.w[0] = whh1hi; pGh1.segs.w[1] = whh1lo;
                   pGh1.C = gate1;
    GemmProb pGi1; pGi1.segs.a[0] = h0h; pGi1.segs.a[1] = h0h;
                   pGi1.segs.w[0] = wih1hi; pGi1.segs.w[1] = wih1lo;
                   pGi1.C = gate0;

    dim3 gridDual(G3 / BN, Nq / BM, 2);   // 12 x 128 x 2
    dim3 gridSingle(G3 / BN, Nq / BM, 1); // 12 x 128
    int combBlocks = (Nq * Hq / 4 + 255) / 256;

    for (int t = 0; t < Tq; t++) {
        // merged: Gh0 = h0 @ Whh0^T  and  Gh1 = h1 @ Whh1^T  (independent)
        gemm_mma<<<gridDual, 256, GEMM_SMEM>>>(pGh0, pGh1);
        combine0<<<combBlocks, 256>>>(gate0, h0, h0h, Wih0, bih0, bhh0);

        // Gi1 = h0n @ Wih1^T
        gemm_mma<<<gridSingle, 256, GEMM_SMEM>>>(pGi1, pGi1);
        combine1<<<combBlocks, 256>>>(gate0, gate1, h1, h1h, bih1, bhh1);

        // fused MLP + prediction (writes g_x and out directly)
        mlp_pred<<<Nq / BM, 256, MP_SMEM>>>(h1h, w1hi, w1lo, b1, W2, b2, out, t);
    }
}

// round 16
// speedup vs baseline: 1.1869x; 1.1439x over previous
#include <cuda_runtime.h>
#include <cuda_fp16.h>
#include <math.h>
#include <stdint.h>

// Problem constants
#define Bq 64
#define Aq 256
#define Hq 512
#define Oq 2
#define Tq 32
#define Nq (Bq*Aq)     // 16384 rows
#define G3 (3*Hq)      // 1536
#define MH (Hq/2)      // 256

// ---------------- device globals (no allocation allowed) --------------------
__device__ float g_h0[Nq*Hq];
__device__ float g_h1[Nq*Hq];
__device__ __half g_h0h[Nq*Hq];
__device__ __half g_h1h[Nq*Hq];
__device__ float g_gate0[Nq*G3];
__device__ float g_gate1[Nq*G3];
__device__ float g_x[Nq*Oq];
__device__ __half g_Whh0hi[G3*Hq], g_Whh0lo[G3*Hq];
__device__ __half g_Wih1hi[G3*Hq], g_Wih1lo[G3*Hq];
__device__ __half g_Whh1hi[G3*Hq], g_Whh1lo[G3*Hq];
__device__ __half g_W1hi[MH*Hq],  g_W1lo[MH*Hq];

// ---------------- helpers ----------------------------------------------------
__device__ __forceinline__ uint32_t smem_u32(const void* p) {
    uint32_t a;
    asm("{ .reg .u64 t; cvta.to.shared.u64 t, %1; cvt.u32.u64 %0, t; }" : "=r"(a) : "l"(p));
    return a;
}
__device__ __forceinline__ void cp_async16(uint32_t dst, const void* src) {
    asm volatile("cp.async.cg.shared.global [%0], [%1], 16;" :: "r"(dst), "l"(src) : "memory");
}
__device__ __forceinline__ void ldmatrix_x4(uint32_t& r0, uint32_t& r1, uint32_t& r2, uint32_t& r3, uint32_t addr) {
    asm volatile("ldmatrix.sync.aligned.m8n8.x4.shared.b16 {%0,%1,%2,%3}, [%4];"
                 : "=r"(r0), "=r"(r1), "=r"(r2), "=r"(r3) : "r"(addr));
}
__device__ __forceinline__ void mma16816(float* d, uint32_t a0, uint32_t a1, uint32_t a2, uint32_t a3,
                                         uint32_t b0, uint32_t b1) {
    asm volatile("mma.sync.aligned.m16n8k16.row.col.f32.f16.f16.f32 "
                 "{%0,%1,%2,%3}, {%4,%5,%6,%7}, {%8,%9}, {%0,%1,%2,%3};"
                 : "+f"(d[0]), "+f"(d[1]), "+f"(d[2]), "+f"(d[3])
                 : "r"(a0), "r"(a1), "r"(a2), "r"(a3), "r"(b0), "r"(b1));
}

// ---------------- gate GEMM: A loaded once, used by BOTH weight halves -------
// C[Nq x G3] = A[Nq x 512] @ (Whi + Wlo)[G3 x 512]^T  (A = fp16 activations)
// tile 128x128, 8 warps as 4x2 (warp tile 32x64). 8 K-chunks of 64 halves;
// each stage holds A chunk + Whi chunk + Wlo chunk. Double buffered,
// one __syncthreads per chunk, 2 CTAs/SM. blockIdx.z selects problem.
#define BM 128
#define BN 128
#define BKH 64
#define ROWB 144
#define OFF_WHI (BM * ROWB)                  // 18432
#define OFF_WLO (OFF_WHI + BN * ROWB)        // 36864
#define STAGE2 ((BM + 2 * BN) * ROWB)        // 55296
#define GEMM_SMEM (2 * STAGE2)               // 110592
#define NCH2 8

struct GemmProb {
    const __half* a;
    const __half* whi;
    const __half* wlo;
    float* C;
};

__global__ __launch_bounds__(256, 2) void gemm_mma(GemmProb p0, GemmProb p1)
{
    extern __shared__ char sm[];
    const GemmProb& p = blockIdx.z ? p1 : p0;

    const int tid  = threadIdx.x;
    const int warp = tid >> 5;
    const int lane = tid & 31;
    const int rowBase = blockIdx.y * BM;
    const int colBase = blockIdx.x * BN;
    const int wr = (warp & 3) * 32;
    const int wc = (warp >> 2) * 64;

    const uint32_t sbase = smem_u32(sm);

    float acc[2][8][4];
#pragma unroll
    for (int i = 0; i < 2; i++)
#pragma unroll
        for (int j = 0; j < 8; j++)
#pragma unroll
            for (int v = 0; v < 4; v++) acc[i][j][v] = 0.0f;

#define LOAD_CHUNK(c, s) do { \
        int _koff = (c) * BKH; \
        const __half* _Ag = p.a   + (size_t)rowBase * Hq + _koff; \
        const __half* _Wh = p.whi + (size_t)colBase * Hq + _koff; \
        const __half* _Wl = p.wlo + (size_t)colBase * Hq + _koff; \
        uint32_t _ab = sbase + (s) * STAGE2; \
        _Pragma("unroll") \
        for (int _i = 0; _i < 4; _i++) { \
            int _lin = tid + _i * 256; \
            int _r = _lin >> 3, _sg = _lin & 7; \
            cp_async16(_ab + _r * ROWB + _sg * 16, _Ag + (size_t)_r * Hq + _sg * 8); \
        } \
        _Pragma("unroll") \
        for (int _i = 0; _i < 4; _i++) { \
            int _lin = tid + _i * 256; \
            int _r = _lin >> 3, _sg = _lin & 7; \
            cp_async16(_ab + OFF_WHI + _r * ROWB + _sg * 16, _Wh + (size_t)_r * Hq + _sg * 8); \
        } \
        _Pragma("unroll") \
        for (int _i = 0; _i < 4; _i++) { \
            int _lin = tid + _i * 256; \
            int _r = _lin >> 3, _sg = _lin & 7; \
            cp_async16(_ab + OFF_WLO + _r * ROWB + _sg * 16, _Wl + (size_t)_r * Hq + _sg * 8); \
        } \
        asm volatile("cp.async.commit_group;" ::: "memory"); \
    } while (0)

    LOAD_CHUNK(0, 0);

    const uint32_t aAddrBase = (wr + (lane & 15)) * ROWB + (lane >> 4) * 16;
    const uint32_t wAddrOff  = (wc + (lane & 7) + ((lane >> 4) & 1) * 8) * ROWB
                             + ((lane >> 3) & 1) * 16;

    for (int c = 0; c < NCH2; c++) {
        asm volatile("cp.async.wait_group 0;" ::: "memory");  // chunk c resident
        __syncthreads();                                      // all done with c-1

        if (c + 1 < NCH2) LOAD_CHUNK(c + 1, (c + 1) & 1);     // async over MMA(c)

        const uint32_t stageOff = sbase + (c & 1) * STAGE2;
#pragma unroll
        for (int ks = 0; ks < 4; ks++) {
            uint32_t af[2][4], bf[4][4];
#pragma unroll
            for (int rt = 0; rt < 2; rt++)
                ldmatrix_x4(af[rt][0], af[rt][1], af[rt][2], af[rt][3],
                            stageOff + aAddrBase + rt * 16 * ROWB + ks * 32);
            // hi pass
#pragma unroll
            for (int cp = 0; cp < 4; cp++)
                ldmatrix_x4(bf[cp][0], bf[cp][1], bf[cp][2], bf[cp][3],
                            stageOff + OFF_WHI + wAddrOff + cp * 16 * ROWB + ks * 32);
#pragma unroll
            for (int rt = 0; rt < 2; rt++)
#pragma unroll
                for (int ct = 0; ct < 8; ct++) {
                    int cp = ct >> 1, hf = (ct & 1) * 2;
                    mma16816(acc[rt][ct], af[rt][0], af[rt][1], af[rt][2], af[rt][3],
                             bf[cp][hf], bf[cp][hf + 1]);
                }
            // lo pass (A frags reused)
#pragma unroll
            for (int cp = 0; cp < 4; cp++)
                ldmatrix_x4(bf[cp][0], bf[cp][1], bf[cp][2], bf[cp][3],
                            stageOff + OFF_WLO + wAddrOff + cp * 16 * ROWB + ks * 32);
#pragma unroll
            for (int rt = 0; rt < 2; rt++)
#pragma unroll
                for (int ct = 0; ct < 8; ct++) {
                    int cp = ct >> 1, hf = (ct & 1) * 2;
                    mma16816(acc[rt][ct], af[rt][0], af[rt][1], af[rt][2], af[rt][3],
                             bf[cp][hf], bf[cp][hf + 1]);
                }
        }
    }

    const int gid = lane >> 2;
    const int tig = lane & 3;
#pragma unroll
    for (int rt = 0; rt < 2; rt++) {
        int row0 = rowBase + wr + rt * 16 + gid;
#pragma unroll
        for (int ct = 0; ct < 8; ct++) {
            int col = colBase + wc + ct * 8 + tig * 2;
            float2 v0 = make_float2(acc[rt][ct][0], acc[rt][ct][1]);
            float2 v1 = make_float2(acc[rt][ct][2], acc[rt][ct][3]);
            *reinterpret_cast<float2*>(p.C + (size_t)row0 * G3 + col) = v0;
            *reinterpret_cast<float2*>(p.C + (size_t)(row0 + 8) * G3 + col) = v1;
        }
    }
#undef LOAD_CHUNK
}

// ---------------- fused MLP + prediction kernel ------------------------------
// 128 rows x all 256 MLP cols per CTA; A chunk shared by both weight halves.
// grid = 128 CTAs, 8 warps = 4 row x 2 col groups (warp tile 32x128).
#define MP_OFF_WHI (BM * ROWB)                 // 18432
#define MP_OFF_WLO (MP_OFF_WHI + MH * ROWB)    // 55296
#define MP_STAGE ((BM + 2 * MH) * ROWB)        // 92160
#define MP_SMEM  (2 * MP_STAGE)                // 184320

__global__ __launch_bounds__(256, 1) void mlp_pred(
    const __half* __restrict__ Ain,
    const __half* __restrict__ Whi,
    const __half* __restrict__ Wlo,
    const float* __restrict__ b1,
    const float* __restrict__ W2,
    const float* __restrict__ b2,
    float* __restrict__ out, int t)
{
    extern __shared__ char sm[];
    __shared__ float sred[2][BM][2];

    const int tid  = threadIdx.x;
    const int warp = tid >> 5;
    const int lane = tid & 31;
    const int rowBase = blockIdx.x * BM;
    const int wr = (warp & 3) * 32;
    const int wc = (warp >> 2) * 128;
    const int cg = warp >> 2;

    const uint32_t sbase = smem_u32(sm);

    float acc[2][16][4];
#pragma unroll
    for (int i = 0; i < 2; i++)
#pragma unroll
        for (int j = 0; j < 16; j++)
#pragma unroll
            for (int v = 0; v < 4; v++) acc[i][j][v] = 0.0f;

#define MP_LOAD(c, s) do { \
        int _koff = (c) * BKH; \
        const __half* _Ag = Ain + (size_t)rowBase * Hq + _koff; \
        const __half* _Wh = Whi + _koff; \
        const __half* _Wl = Wlo + _koff; \
        uint32_t _ab = sbase + (s) * MP_STAGE; \
        _Pragma("unroll") \
        for (int _i = 0; _i < 4; _i++) { \
            int _lin = tid + _i * 256; \
            int _r = _lin >> 3, _sg = _lin & 7; \
            cp_async16(_ab + _r * ROWB + _sg * 16, _Ag + (size_t)_r * Hq + _sg * 8); \
        } \
        _Pragma("unroll") \
        for (int _i = 0; _i < 8; _i++) { \
            int _lin = tid + _i * 256; \
            int _r = _lin >> 3, _sg = _lin & 7; \
            cp_async16(_ab + MP_OFF_WHI + _r * ROWB + _sg * 16, _Wh + (size_t)_r * Hq + _sg * 8); \
        } \
        _Pragma("unroll") \
        for (int _i = 0; _i < 8; _i++) { \
            int _lin = tid + _i * 256; \
            int _r = _lin >> 3, _sg = _lin & 7; \
            cp_async16(_ab + MP_OFF_WLO + _r * ROWB + _sg * 16, _Wl + (size_t)_r * Hq + _sg * 8); \
        } \
        asm volatile("cp.async.commit_group;" ::: "memory"); \
    } while (0)

    MP_LOAD(0, 0);

    const uint32_t aAddrBase = (wr + (lane & 15)) * ROWB + (lane >> 4) * 16;
    const uint32_t wAddrOff  = (wc + (lane & 7) + ((lane >> 4) & 1) * 8) * ROWB
                             + ((lane >> 3) & 1) * 16;

    for (int c = 0; c < NCH2; c++) {
        asm volatile("cp.async.wait_group 0;" ::: "memory");
        __syncthreads();

        if (c + 1 < NCH2) MP_LOAD(c + 1, (c + 1) & 1);

        const uint32_t stageOff = sbase + (c & 1) * MP_STAGE;
#pragma unroll
        for (int ks = 0; ks < 4; ks++) {
            uint32_t af[2][4], bf[8][4];
#pragma unroll
            for (int rt = 0; rt < 2; rt++)
                ldmatrix_x4(af[rt][0], af[rt][1], af[rt][2], af[rt][3],
                            stageOff + aAddrBase + rt * 16 * ROWB + ks * 32);
#pragma unroll
            for (int cp = 0; cp < 8; cp++)
                ldmatrix_x4(bf[cp][0], bf[cp][1], bf[cp][2], bf[cp][3],
                            stageOff + MP_OFF_WHI + wAddrOff + cp * 16 * ROWB + ks * 32);
#pragma unroll
            for (int rt = 0; rt < 2; rt++)
#pragma unroll
                for (int ct = 0; ct < 16; ct++) {
                    int cp = ct >> 1, hf = (ct & 1) * 2;
                    mma16816(acc[rt][ct], af[rt][0], af[rt][1], af[rt][2], af[rt][3],
                             bf[cp][hf], bf[cp][hf + 1]);
                }
#pragma unroll
            for (int cp = 0; cp < 8; cp++)
                ldmatrix_x4(bf[cp][0], bf[cp][1], bf[cp][2], bf[cp][3],
                            stageOff + MP_OFF_WLO + wAddrOff + cp * 16 * ROWB + ks * 32);
#pragma unroll
            for (int rt = 0; rt < 2; rt++)
#pragma unroll
                for (int ct = 0; ct < 16; ct++) {
                    int cp = ct >> 1, hf = (ct & 1) * 2;
                    mma16816(acc[rt][ct], af[rt][0], af[rt][1], af[rt][2], af[rt][3],
                             bf[cp][hf], bf[cp][hf + 1]);
                }
        }
    }
#undef MP_LOAD

    // ---- fused pred epilogue -----------------------------------------------
    const int gid = lane >> 2;
    const int tig = lane & 3;
    float s[2][4];
#pragma unroll
    for (int d = 0; d < 2; d++)
#pragma unroll
        for (int k = 0; k < 4; k++) s[d][k] = 0.0f;

#pragma unroll
    for (int rt = 0; rt < 2; rt++)
#pragma unroll
        for (int ct = 0; ct < 16; ct++) {
            int col = wc + ct * 8 + tig * 2;
            float b1a = b1[col], b1b = b1[col + 1];
            float w0a = W2[col],      w0b = W2[col + 1];
            float w1a = W2[MH + col], w1b = W2[MH + col + 1];
            float m0 = fmaxf(acc[rt][ct][0] + b1a, 0.f);
            float m1 = fmaxf(acc[rt][ct][1] + b1b, 0.f);
            float m2 = fmaxf(acc[rt][ct][2] + b1a, 0.f);
            float m3 = fmaxf(acc[rt][ct][3] + b1b, 0.f);
            s[0][rt * 2 + 0] += m0 * w0a + m1 * w0b;
            s[1][rt * 2 + 0] += m0 * w1a + m1 * w1b;
            s[0][rt * 2 + 1] += m2 * w0a + m3 * w0b;
            s[1][rt * 2 + 1] += m2 * w1a + m3 * w1b;
        }

#pragma unroll
    for (int off = 1; off <= 2; off <<= 1)
#pragma unroll
        for (int d = 0; d < 2; d++)
#pragma unroll
            for (int k = 0; k < 4; k++)
                s[d][k] += __shfl_xor_sync(0xFFFFFFFFu, s[d][k], off);

    if (tig == 0) {
#pragma unroll
        for (int rt = 0; rt < 2; rt++)
#pragma unroll
            for (int h = 0; h < 2; h++) {
                int row = wr + rt * 16 + gid + h * 8;
                sred[0][row][cg] = s[0][rt * 2 + h];
                sred[1][row][cg] = s[1][rt * 2 + h];
            }
    }
    __syncthreads();

    if (tid < BM) {
        int row = tid;
        float r0 = sred[0][row][0] + sred[0][row][1] + b2[0];
        float r1 = sred[1][row][0] + sred[1][row][1] + b2[1];
        int grow = rowBase + row;
        g_x[grow * 2 + 0] = r0;
        g_x[grow * 2 + 1] = r1;
        int b = grow >> 8;
        int a = grow & (Aq - 1);
        float* o = out + (((size_t)b * Tq + t) * Aq + a) * Oq;
        o[0] = r0;
        o[1] = r1;
    }
}

// ---------------- fused weight split (fp16 hi/lo, all 4 weights) -------------
#define WSZ (G3*Hq)
#define SPLIT_TOTAL (3*WSZ + MH*Hq)
__global__ void split_all(const float* __restrict__ Whh0, const float* __restrict__ Wih1,
                          const float* __restrict__ Whh1, const float* __restrict__ W1)
{
    int idx = blockIdx.x * blockDim.x + threadIdx.x;
    if (idx >= SPLIT_TOTAL) return;
    const float* src; __half* hi; __half* lo; int i;
    if (idx < WSZ)            { src = Whh0; hi = g_Whh0hi; lo = g_Whh0lo; i = idx; }
    else if (idx < 2*WSZ)     { src = Wih1; hi = g_Wih1hi; lo = g_Wih1lo; i = idx - WSZ; }
    else if (idx < 3*WSZ)     { src = Whh1; hi = g_Whh1hi; lo = g_Whh1lo; i = idx - 2*WSZ; }
    else                      { src = W1;   hi = g_W1hi;   lo = g_W1lo;   i = idx - 3*WSZ; }
    float v = src[i];
    __half h = __float2half_rn(v);
    hi[i] = h;
    lo[i] = __float2half_rn(v - __half2float(h));
}

// ---------------- init -------------------------------------------------------
__global__ void init_kernel(const float* __restrict__ social,
                            const float* __restrict__ lastpos)
{
    int idx = blockIdx.x * blockDim.x + threadIdx.x;
    if (idx < Nq * Hq) {
        int i = idx >> 9;
        int cch = idx & (Hq - 1);
        int b = i & (Bq - 1);
        int a = i >> 6;
        float v = social[(b * Aq + a) * Hq + cch];
        g_h0[idx] = v;
        g_h1[idx] = v;
        __half h = __float2half_rn(v);
        g_h0h[idx] = h;
        g_h1h[idx] = h;
    }
    if (idx < Nq * Oq) g_x[idx] = lastpos[idx];
}

// ---------------- GRU combine layer 0 (vectorized x4, inline x@Wih0) ---------
__global__ __launch_bounds__(256, 3) void combine0(
                         const float* __restrict__ gh,
                         float* __restrict__ h,
                         __half* __restrict__ hh,
                         const float* __restrict__ Wih0,
                         const float* __restrict__ bih,
                         const float* __restrict__ bhh)
{
    int v4 = blockIdx.x * blockDim.x + threadIdx.x;
    if (v4 >= Nq * Hq / 4) return;
    int idx = v4 * 4;
    int i = idx >> 9;
    int j = idx & (Hq - 1);

    float x0 = g_x[i * 2 + 0];
    float x1 = g_x[i * 2 + 1];

    const float* g = gh + (size_t)i * G3;
    float4 gr = *(const float4*)(g + 0 * Hq + j);
    float4 gz = *(const float4*)(g + 1 * Hq + j);
    float4 gn = *(const float4*)(g + 2 * Hq + j);
    float4 br_i = *(const float4*)(bih + 0 * Hq + j);
    float4 bz_i = *(const float4*)(bih + 1 * Hq + j);
    float4 bn_i = *(const float4*)(bih + 2 * Hq + j);
    float4 br_h = *(const float4*)(bhh + 0 * Hq + j);
    float4 bz_h = *(const float4*)(bhh + 1 * Hq + j);
    float4 bn_h = *(const float4*)(bhh + 2 * Hq + j);
    float4 hp = *(const float4*)(h + idx);

    float4 wr0 = *(const float4*)(Wih0 + (0 * Hq + j) * 2);
    float4 wr1 = *(const float4*)(Wih0 + (0 * Hq + j) * 2 + 4);
    float4 wz0 = *(const float4*)(Wih0 + (1 * Hq + j) * 2);
    float4 wz1 = *(const float4*)(Wih0 + (1 * Hq + j) * 2 + 4);
    float4 wn0 = *(const float4*)(Wih0 + (2 * Hq + j) * 2);
    float4 wn1 = *(const float4*)(Wih0 + (2 * Hq + j) * 2 + 4);

    float ho[4]; __half hhv[4];
#pragma unroll
    for (int u = 0; u < 4; u++) {
        float wir0 = (u < 2) ? ((u == 0) ? wr0.x : wr0.z) : ((u == 2) ? wr1.x : wr1.z);
        float wir1 = (u < 2) ? ((u == 0) ? wr0.y : wr0.w) : ((u == 2) ? wr1.y : wr1.w);
        float wiz0 = (u < 2) ? ((u == 0) ? wz0.x : wz0.z) : ((u == 2) ? wz1.x : wz1.z);
        float wiz1 = (u < 2) ? ((u == 0) ? wz0.y : wz0.w) : ((u == 2) ? wz1.y : wz1.w);
        float win0 = (u < 2) ? ((u == 0) ? wn0.x : wn0.z) : ((u == 2) ? wn1.x : wn1.z);
        float win1 = (u < 2) ? ((u == 0) ? wn0.y : wn0.w) : ((u == 2) ? wn1.y : wn1.w);

        float ir  = x0 * wir0 + x1 * wir1 + (&br_i.x)[u];
        float iz  = x0 * wiz0 + x1 * wiz1 + (&bz_i.x)[u];
        float in_ = x0 * win0 + x1 * win1 + (&bn_i.x)[u];
        float hr = (&gr.x)[u] + (&br_h.x)[u];
        float hz = (&gz.x)[u] + (&bz_h.x)[u];
        float hn = (&gn.x)[u] + (&bn_h.x)[u];

        float r = 1.0f / (1.0f + expf(-(ir + hr)));
        float z = 1.0f / (1.0f + expf(-(iz + hz)));
        float n = tanhf(in_ + r * hn);
        float v = (1.0f - z) * n + z * (&hp.x)[u];
        ho[u] = v;
        hhv[u] = __float2half_rn(v);
    }
    *(float4*)(h + idx) = make_float4(ho[0], ho[1], ho[2], ho[3]);
    *(uint2*)(hh + idx) = *(uint2*)hhv;
}

// ---------------- GRU combine layer 1 (vectorized x4) ------------------------
__global__ __launch_bounds__(256, 3) void combine1(
                         const float* __restrict__ gi,
                         const float* __restrict__ gh,
                         float* __restrict__ h,
                         __half* __restrict__ hh,
                         const float* __restrict__ bih,
                         const float* __restrict__ bhh)
{
    int v4 = blockIdx.x * blockDim.x + threadIdx.x;
    if (v4 >= Nq * Hq / 4) return;
    int idx = v4 * 4;
    int i = idx >> 9;
    int j = idx & (Hq - 1);

    const float* a = gi + (size_t)i * G3;
    const float* g = gh + (size_t)i * G3;

    float4 ar = *(const float4*)(a + 0 * Hq + j);
    float4 az = *(const float4*)(a + 1 * Hq + j);
    float4 an = *(const float4*)(a + 2 * Hq + j);
    float4 gr = *(const float4*)(g + 0 * Hq + j);
    float4 gz = *(const float4*)(g + 1 * Hq + j);
    float4 gn = *(const float4*)(g + 2 * Hq + j);
    float4 br_i = *(const float4*)(bih + 0 * Hq + j);
    float4 bz_i = *(const float4*)(bih + 1 * Hq + j);
    float4 bn_i = *(const float4*)(bih + 2 * Hq + j);
    float4 br_h = *(const float4*)(bhh + 0 * Hq + j);
    float4 bz_h = *(const float4*)(bhh + 1 * Hq + j);
    float4 bn_h = *(const float4*)(bhh + 2 * Hq + j);
    float4 hp = *(const float4*)(h + idx);

    float ho[4]; __half hhv[4];
#pragma unroll
    for (int u = 0; u < 4; u++) {
        float ir  = (&ar.x)[u] + (&br_i.x)[u];
        float iz  = (&az.x)[u] + (&bz_i.x)[u];
        float in_ = (&an.x)[u] + (&bn_i.x)[u];
        float hr  = (&gr.x)[u] + (&br_h.x)[u];
        float hz  = (&gz.x)[u] + (&bz_h.x)[u];
        float hn  = (&gn.x)[u] + (&bn_h.x)[u];

        float r = 1.0f / (1.0f + expf(-(ir + hr)));
        float z = 1.0f / (1.0f + expf(-(iz + hz)));
        float n = tanhf(in_ + r * hn);
        float v = (1.0f - z) * n + z * (&hp.x)[u];
        ho[u] = v;
        hhv[u] = __float2half_rn(v);
    }
    *(float4*)(h + idx) = make_float4(ho[0], ho[1], ho[2], ho[3]);
    *(uint2*)(hh + idx) = *(uint2*)hhv;
}

// ---------------- launch -----------------------------------------------------
extern "C" void kernel_launch(void* const* d_in, const int* in_sizes, int n_in,
                              void* d_out, int out_size)
{
    const float* social  = (const float*)d_in[0];
    const float* lastpos = (const float*)d_in[1];
    const float* Wih0    = (const float*)d_in[2];
    const float* Whh0    = (const float*)d_in[3];
    const float* bih0    = (const float*)d_in[4];
    const float* bhh0    = (const float*)d_in[5];
    const float* Wih1    = (const float*)d_in[6];
    const float* Whh1    = (const float*)d_in[7];
    const float* bih1    = (const float*)d_in[8];
    const float* bhh1    = (const float*)d_in[9];
    const float* W1      = (const float*)d_in[10];
    const float* b1      = (const float*)d_in[11];
    const float* W2      = (const float*)d_in[12];
    const float* b2      = (const float*)d_in[13];
    float* out = (float*)d_out;

    float *h0, *h1, *gate0, *gate1;
    __half *h0h, *h1h;
    __half *whh0hi, *whh0lo, *wih1hi, *wih1lo, *whh1hi, *whh1lo, *w1hi, *w1lo;
    cudaGetSymbolAddress((void**)&h0,    g_h0);
    cudaGetSymbolAddress((void**)&h1,    g_h1);
    cudaGetSymbolAddress((void**)&gate0, g_gate0);
    cudaGetSymbolAddress((void**)&gate1, g_gate1);
    cudaGetSymbolAddress((void**)&h0h,   g_h0h);
    cudaGetSymbolAddress((void**)&h1h,   g_h1h);
    cudaGetSymbolAddress((void**)&whh0hi, g_Whh0hi);
    cudaGetSymbolAddress((void**)&whh0lo, g_Whh0lo);
    cudaGetSymbolAddress((void**)&wih1hi, g_Wih1hi);
    cudaGetSymbolAddress((void**)&wih1lo, g_Wih1lo);
    cudaGetSymbolAddress((void**)&whh1hi, g_Whh1hi);
    cudaGetSymbolAddress((void**)&whh1lo, g_Whh1lo);
    cudaGetSymbolAddress((void**)&w1hi,  g_W1hi);
    cudaGetSymbolAddress((void**)&w1lo,  g_W1lo);

    cudaFuncSetAttribute(gemm_mma, cudaFuncAttributeMaxDynamicSharedMemorySize, GEMM_SMEM);
    cudaFuncSetAttribute(mlp_pred, cudaFuncAttributeMaxDynamicSharedMemorySize, MP_SMEM);

    split_all<<<(SPLIT_TOTAL + 255) / 256, 256>>>(Whh0, Wih1, Whh1, W1);
    init_kernel<<<(Nq * Hq + 255) / 256, 256>>>(social, lastpos);

    GemmProb pGh0; pGh0.a = h0h; pGh0.whi = whh0hi; pGh0.wlo = whh0lo; pGh0.C = gate0;
    GemmProb pGh1; pGh1.a = h1h; pGh1.whi = whh1hi; pGh1.wlo = whh1lo; pGh1.C = gate1;
    GemmProb pGi1; pGi1.a = h0h; pGi1.whi = wih1hi; pGi1.wlo = wih1lo; pGi1.C = gate0;

    dim3 gridDual(G3 / BN, Nq / BM, 2);
    dim3 gridSingle(G3 / BN, Nq / BM, 1);
    int combBlocks = (Nq * Hq / 4 + 255) / 256;

    for (int t = 0; t < Tq; t++) {
        gemm_mma<<<gridDual, 256, GEMM_SMEM>>>(pGh0, pGh1);
        combine0<<<combBlocks, 256>>>(gate0, h0, h0h, Wih0, bih0, bhh0);

        gemm_mma<<<gridSingle, 256, GEMM_SMEM>>>(pGi1, pGi1);
        combine1<<<combBlocks, 256>>>(gate0, gate1, h1, h1h, bih1, bhh1);

        mlp_pred<<<Nq / BM, 256, MP_SMEM>>>(h1h, w1hi, w1lo, b1, W2, b2, out, t);
    }
}

// round 17
// speedup vs baseline: 1.2161x; 1.0245x over previous
#include <cuda_runtime.h>
#include <cuda_fp16.h>
#include <math.h>
#include <stdint.h>

// Problem constants
#define Bq 64
#define Aq 256
#define Hq 512
#define Oq 2
#define Tq 32
#define Nq (Bq*Aq)     // 16384 rows
#define G3 (3*Hq)      // 1536
#define MH (Hq/2)      // 256

// ---------------- device globals (no allocation allowed) --------------------
__device__ float g_h0[Nq*Hq];
__device__ float g_h1[Nq*Hq];
__device__ __half g_h0h[Nq*Hq];
__device__ __half g_h1h[Nq*Hq];
__device__ __half g_gate0[Nq*G3];     // fp16 gate pre-activations
__device__ __half g_gate1[Nq*G3];
__device__ float g_x[Nq*Oq];
__device__ __half g_Whh0hi[G3*Hq], g_Whh0lo[G3*Hq];
__device__ __half g_Wih1hi[G3*Hq], g_Wih1lo[G3*Hq];
__device__ __half g_Whh1hi[G3*Hq], g_Whh1lo[G3*Hq];
__device__ __half g_W1hi[MH*Hq],  g_W1lo[MH*Hq];

// ---------------- helpers ----------------------------------------------------
__device__ __forceinline__ uint32_t smem_u32(const void* p) {
    uint32_t a;
    asm("{ .reg .u64 t; cvta.to.shared.u64 t, %1; cvt.u32.u64 %0, t; }" : "=r"(a) : "l"(p));
    return a;
}
__device__ __forceinline__ void cp_async16(uint32_t dst, const void* src) {
    asm volatile("cp.async.cg.shared.global [%0], [%1], 16;" :: "r"(dst), "l"(src) : "memory");
}
__device__ __forceinline__ void ldmatrix_x4(uint32_t& r0, uint32_t& r1, uint32_t& r2, uint32_t& r3, uint32_t addr) {
    asm volatile("ldmatrix.sync.aligned.m8n8.x4.shared.b16 {%0,%1,%2,%3}, [%4];"
                 : "=r"(r0), "=r"(r1), "=r"(r2), "=r"(r3) : "r"(addr));
}
__device__ __forceinline__ void mma16816(float* d, uint32_t a0, uint32_t a1, uint32_t a2, uint32_t a3,
                                         uint32_t b0, uint32_t b1) {
    asm volatile("mma.sync.aligned.m16n8k16.row.col.f32.f16.f16.f32 "
                 "{%0,%1,%2,%3}, {%4,%5,%6,%7}, {%8,%9}, {%0,%1,%2,%3};"
                 : "+f"(d[0]), "+f"(d[1]), "+f"(d[2]), "+f"(d[3])
                 : "r"(a0), "r"(a1), "r"(a2), "r"(a3), "r"(b0), "r"(b1));
}
__device__ __forceinline__ void unpack4h(uint2 p, float* f) {
    __half2 a0 = *reinterpret_cast<__half2*>(&p.x);
    __half2 a1 = *reinterpret_cast<__half2*>(&p.y);
    float2 f0 = __half22float2(a0), f1 = __half22float2(a1);
    f[0] = f0.x; f[1] = f0.y; f[2] = f1.x; f[3] = f1.y;
}

// ---------------- gate GEMM: A loaded once, used by BOTH weight halves -------
// C(fp16)[Nq x G3] = A[Nq x 512] @ (Whi + Wlo)[G3 x 512]^T
// tile 128x128, 8 warps as 4x2 (warp tile 32x64). 8 K-chunks of 64 halves;
// each stage holds A + Whi + Wlo chunk. Double buffered, one sync per chunk,
// 2 CTAs/SM. blockIdx.z selects problem.
#define BM 128
#define BN 128
#define BKH 64
#define ROWB 144
#define OFF_WHI (BM * ROWB)
#define OFF_WLO (OFF_WHI + BN * ROWB)
#define STAGE2 ((BM + 2 * BN) * ROWB)        // 55296
#define GEMM_SMEM (2 * STAGE2)               // 110592
#define NCH2 8

struct GemmProb {
    const __half* a;
    const __half* whi;
    const __half* wlo;
    __half* C;
};

__global__ __launch_bounds__(256, 2) void gemm_mma(GemmProb p0, GemmProb p1)
{
    extern __shared__ char sm[];
    const GemmProb& p = blockIdx.z ? p1 : p0;

    const int tid  = threadIdx.x;
    const int warp = tid >> 5;
    const int lane = tid & 31;
    const int rowBase = blockIdx.y * BM;
    const int colBase = blockIdx.x * BN;
    const int wr = (warp & 3) * 32;
    const int wc = (warp >> 2) * 64;

    const uint32_t sbase = smem_u32(sm);

    float acc[2][8][4];
#pragma unroll
    for (int i = 0; i < 2; i++)
#pragma unroll
        for (int j = 0; j < 8; j++)
#pragma unroll
            for (int v = 0; v < 4; v++) acc[i][j][v] = 0.0f;

#define LOAD_CHUNK(c, s) do { \
        int _koff = (c) * BKH; \
        const __half* _Ag = p.a   + (size_t)rowBase * Hq + _koff; \
        const __half* _Wh = p.whi + (size_t)colBase * Hq + _koff; \
        const __half* _Wl = p.wlo + (size_t)colBase * Hq + _koff; \
        uint32_t _ab = sbase + (s) * STAGE2; \
        _Pragma("unroll") \
        for (int _i = 0; _i < 4; _i++) { \
            int _lin = tid + _i * 256; \
            int _r = _lin >> 3, _sg = _lin & 7; \
            cp_async16(_ab + _r * ROWB + _sg * 16, _Ag + (size_t)_r * Hq + _sg * 8); \
        } \
        _Pragma("unroll") \
        for (int _i = 0; _i < 4; _i++) { \
            int _lin = tid + _i * 256; \
            int _r = _lin >> 3, _sg = _lin & 7; \
            cp_async16(_ab + OFF_WHI + _r * ROWB + _sg * 16, _Wh + (size_t)_r * Hq + _sg * 8); \
        } \
        _Pragma("unroll") \
        for (int _i = 0; _i < 4; _i++) { \
            int _lin = tid + _i * 256; \
            int _r = _lin >> 3, _sg = _lin & 7; \
            cp_async16(_ab + OFF_WLO + _r * ROWB + _sg * 16, _Wl + (size_t)_r * Hq + _sg * 8); \
        } \
        asm volatile("cp.async.commit_group;" ::: "memory"); \
    } while (0)

    LOAD_CHUNK(0, 0);

    const uint32_t aAddrBase = (wr + (lane & 15)) * ROWB + (lane >> 4) * 16;
    const uint32_t wAddrOff  = (wc + (lane & 7) + ((lane >> 4) & 1) * 8) * ROWB
                             + ((lane >> 3) & 1) * 16;

    for (int c = 0; c < NCH2; c++) {
        asm volatile("cp.async.wait_group 0;" ::: "memory");
        __syncthreads();

        if (c + 1 < NCH2) LOAD_CHUNK(c + 1, (c + 1) & 1);

        const uint32_t stageOff = sbase + (c & 1) * STAGE2;
#pragma unroll
        for (int ks = 0; ks < 4; ks++) {
            uint32_t af[2][4], bf[4][4];
#pragma unroll
            for (int rt = 0; rt < 2; rt++)
                ldmatrix_x4(af[rt][0], af[rt][1], af[rt][2], af[rt][3],
                            stageOff + aAddrBase + rt * 16 * ROWB + ks * 32);
#pragma unroll
            for (int cp = 0; cp < 4; cp++)
                ldmatrix_x4(bf[cp][0], bf[cp][1], bf[cp][2], bf[cp][3],
                            stageOff + OFF_WHI + wAddrOff + cp * 16 * ROWB + ks * 32);
#pragma unroll
            for (int rt = 0; rt < 2; rt++)
#pragma unroll
                for (int ct = 0; ct < 8; ct++) {
                    int cp = ct >> 1, hf = (ct & 1) * 2;
                    mma16816(acc[rt][ct], af[rt][0], af[rt][1], af[rt][2], af[rt][3],
                             bf[cp][hf], bf[cp][hf + 1]);
                }
#pragma unroll
            for (int cp = 0; cp < 4; cp++)
                ldmatrix_x4(bf[cp][0], bf[cp][1], bf[cp][2], bf[cp][3],
                            stageOff + OFF_WLO + wAddrOff + cp * 16 * ROWB + ks * 32);
#pragma unroll
            for (int rt = 0; rt < 2; rt++)
#pragma unroll
                for (int ct = 0; ct < 8; ct++) {
                    int cp = ct >> 1, hf = (ct & 1) * 2;
                    mma16816(acc[rt][ct], af[rt][0], af[rt][1], af[rt][2], af[rt][3],
                             bf[cp][hf], bf[cp][hf + 1]);
                }
        }
    }

    const int gid = lane >> 2;
    const int tig = lane & 3;
#pragma unroll
    for (int rt = 0; rt < 2; rt++) {
        int row0 = rowBase + wr + rt * 16 + gid;
#pragma unroll
        for (int ct = 0; ct < 8; ct++) {
            int col = colBase + wc + ct * 8 + tig * 2;
            __half2 h0 = __floats2half2_rn(acc[rt][ct][0], acc[rt][ct][1]);
            __half2 h1 = __floats2half2_rn(acc[rt][ct][2], acc[rt][ct][3]);
            *reinterpret_cast<__half2*>(p.C + (size_t)row0 * G3 + col) = h0;
            *reinterpret_cast<__half2*>(p.C + (size_t)(row0 + 8) * G3 + col) = h1;
        }
    }
#undef LOAD_CHUNK
}

// ---------------- fused MLP + prediction kernel ------------------------------
#define MP_OFF_WHI (BM * ROWB)
#define MP_OFF_WLO (MP_OFF_WHI + MH * ROWB)
#define MP_STAGE ((BM + 2 * MH) * ROWB)        // 92160
#define MP_SMEM  (2 * MP_STAGE)                // 184320

__global__ __launch_bounds__(256, 1) void mlp_pred(
    const __half* __restrict__ Ain,
    const __half* __restrict__ Whi,
    const __half* __restrict__ Wlo,
    const float* __restrict__ b1,
    const float* __restrict__ W2,
    const float* __restrict__ b2,
    float* __restrict__ out, int t)
{
    extern __shared__ char sm[];
    __shared__ float sred[2][BM][2];

    const int tid  = threadIdx.x;
    const int warp = tid >> 5;
    const int lane = tid & 31;
    const int rowBase = blockIdx.x * BM;
    const int wr = (warp & 3) * 32;
    const int wc = (warp >> 2) * 128;
    const int cg = warp >> 2;

    const uint32_t sbase = smem_u32(sm);

    float acc[2][16][4];
#pragma unroll
    for (int i = 0; i < 2; i++)
#pragma unroll
        for (int j = 0; j < 16; j++)
#pragma unroll
            for (int v = 0; v < 4; v++) acc[i][j][v] = 0.0f;

#define MP_LOAD(c, s) do { \
        int _koff = (c) * BKH; \
        const __half* _Ag = Ain + (size_t)rowBase * Hq + _koff; \
        const __half* _Wh = Whi + _koff; \
        const __half* _Wl = Wlo + _koff; \
        uint32_t _ab = sbase + (s) * MP_STAGE; \
        _Pragma("unroll") \
        for (int _i = 0; _i < 4; _i++) { \
            int _lin = tid + _i * 256; \
            int _r = _lin >> 3, _sg = _lin & 7; \
            cp_async16(_ab + _r * ROWB + _sg * 16, _Ag + (size_t)_r * Hq + _sg * 8); \
        } \
        _Pragma("unroll") \
        for (int _i = 0; _i < 8; _i++) { \
            int _lin = tid + _i * 256; \
            int _r = _lin >> 3, _sg = _lin & 7; \
            cp_async16(_ab + MP_OFF_WHI + _r * ROWB + _sg * 16, _Wh + (size_t)_r * Hq + _sg * 8); \
        } \
        _Pragma("unroll") \
        for (int _i = 0; _i < 8; _i++) { \
            int _lin = tid + _i * 256; \
            int _r = _lin >> 3, _sg = _lin & 7; \
            cp_async16(_ab + MP_OFF_WLO + _r * ROWB + _sg * 16, _Wl + (size_t)_r * Hq + _sg * 8); \
        } \
        asm volatile("cp.async.commit_group;" ::: "memory"); \
    } while (0)

    MP_LOAD(0, 0);

    const uint32_t aAddrBase = (wr + (lane & 15)) * ROWB + (lane >> 4) * 16;
    const uint32_t wAddrOff  = (wc + (lane & 7) + ((lane >> 4) & 1) * 8) * ROWB
                             + ((lane >> 3) & 1) * 16;

    for (int c = 0; c < NCH2; c++) {
        asm volatile("cp.async.wait_group 0;" ::: "memory");
        __syncthreads();

        if (c + 1 < NCH2) MP_LOAD(c + 1, (c + 1) & 1);

        const uint32_t stageOff = sbase + (c & 1) * MP_STAGE;
#pragma unroll
        for (int ks = 0; ks < 4; ks++) {
            uint32_t af[2][4], bf[8][4];
#pragma unroll
            for (int rt = 0; rt < 2; rt++)
                ldmatrix_x4(af[rt][0], af[rt][1], af[rt][2], af[rt][3],
                            stageOff + aAddrBase + rt * 16 * ROWB + ks * 32);
#pragma unroll
            for (int cp = 0; cp < 8; cp++)
                ldmatrix_x4(bf[cp][0], bf[cp][1], bf[cp][2], bf[cp][3],
                            stageOff + MP_OFF_WHI + wAddrOff + cp * 16 * ROWB + ks * 32);
#pragma unroll
            for (int rt = 0; rt < 2; rt++)
#pragma unroll
                for (int ct = 0; ct < 16; ct++) {
                    int cp = ct >> 1, hf = (ct & 1) * 2;
                    mma16816(acc[rt][ct], af[rt][0], af[rt][1], af[rt][2], af[rt][3],
                             bf[cp][hf], bf[cp][hf + 1]);
                }
#pragma unroll
            for (int cp = 0; cp < 8; cp++)
                ldmatrix_x4(bf[cp][0], bf[cp][1], bf[cp][2], bf[cp][3],
                            stageOff + MP_OFF_WLO + wAddrOff + cp * 16 * ROWB + ks * 32);
#pragma unroll
            for (int rt = 0; rt < 2; rt++)
#pragma unroll
                for (int ct = 0; ct < 16; ct++) {
                    int cp = ct >> 1, hf = (ct & 1) * 2;
                    mma16816(acc[rt][ct], af[rt][0], af[rt][1], af[rt][2], af[rt][3],
                             bf[cp][hf], bf[cp][hf + 1]);
                }
        }
    }
#undef MP_LOAD

    const int gid = lane >> 2;
    const int tig = lane & 3;
    float s[2][4];
#pragma unroll
    for (int d = 0; d < 2; d++)
#pragma unroll
        for (int k = 0; k < 4; k++) s[d][k] = 0.0f;

#pragma unroll
    for (int rt = 0; rt < 2; rt++)
#pragma unroll
        for (int ct = 0; ct < 16; ct++) {
            int col = wc + ct * 8 + tig * 2;
            float b1a = b1[col], b1b = b1[col + 1];
            float w0a = W2[col],      w0b = W2[col + 1];
            float w1a = W2[MH + col], w1b = W2[MH + col + 1];
            float m0 = fmaxf(acc[rt][ct][0] + b1a, 0.f);
            float m1 = fmaxf(acc[rt][ct][1] + b1b, 0.f);
            float m2 = fmaxf(acc[rt][ct][2] + b1a, 0.f);
            float m3 = fmaxf(acc[rt][ct][3] + b1b, 0.f);
            s[0][rt * 2 + 0] += m0 * w0a + m1 * w0b;
            s[1][rt * 2 + 0] += m0 * w1a + m1 * w1b;
            s[0][rt * 2 + 1] += m2 * w0a + m3 * w0b;
            s[1][rt * 2 + 1] += m2 * w1a + m3 * w1b;
        }

#pragma unroll
    for (int off = 1; off <= 2; off <<= 1)
#pragma unroll
        for (int d = 0; d < 2; d++)
#pragma unroll
            for (int k = 0; k < 4; k++)
                s[d][k] += __shfl_xor_sync(0xFFFFFFFFu, s[d][k], off);

    if (tig == 0) {
#pragma unroll
        for (int rt = 0; rt < 2; rt++)
#pragma unroll
            for (int h = 0; h < 2; h++) {
                int row = wr + rt * 16 + gid + h * 8;
                sred[0][row][cg] = s[0][rt * 2 + h];
                sred[1][row][cg] = s[1][rt * 2 + h];
            }
    }
    __syncthreads();

    if (tid < BM) {
        int row = tid;
        float r0 = sred[0][row][0] + sred[0][row][1] + b2[0];
        float r1 = sred[1][row][0] + sred[1][row][1] + b2[1];
        int grow = rowBase + row;
        g_x[grow * 2 + 0] = r0;
        g_x[grow * 2 + 1] = r1;
        int b = grow >> 8;
        int a = grow & (Aq - 1);
        float* o = out + (((size_t)b * Tq + t) * Aq + a) * Oq;
        o[0] = r0;
        o[1] = r1;
    }
}

// ---------------- fused weight split (fp16 hi/lo, all 4 weights) -------------
#define WSZ (G3*Hq)
#define SPLIT_TOTAL (3*WSZ + MH*Hq)
__global__ void split_all(const float* __restrict__ Whh0, const float* __restrict__ Wih1,
                          const float* __restrict__ Whh1, const float* __restrict__ W1)
{
    int idx = blockIdx.x * blockDim.x + threadIdx.x;
    if (idx >= SPLIT_TOTAL) return;
    const float* src; __half* hi; __half* lo; int i;
    if (idx < WSZ)            { src = Whh0; hi = g_Whh0hi; lo = g_Whh0lo; i = idx; }
    else if (idx < 2*WSZ)     { src = Wih1; hi = g_Wih1hi; lo = g_Wih1lo; i = idx - WSZ; }
    else if (idx < 3*WSZ)     { src = Whh1; hi = g_Whh1hi; lo = g_Whh1lo; i = idx - 2*WSZ; }
    else                      { src = W1;   hi = g_W1hi;   lo = g_W1lo;   i = idx - 3*WSZ; }
    float v = src[i];
    __half h = __float2half_rn(v);
    hi[i] = h;
    lo[i] = __float2half_rn(v - __half2float(h));
}

// ---------------- init -------------------------------------------------------
__global__ void init_kernel(const float* __restrict__ social,
                            const float* __restrict__ lastpos)
{
    int idx = blockIdx.x * blockDim.x + threadIdx.x;
    if (idx < Nq * Hq) {
        int i = idx >> 9;
        int cch = idx & (Hq - 1);
        int b = i & (Bq - 1);
        int a = i >> 6;
        float v = social[(b * Aq + a) * Hq + cch];
        g_h0[idx] = v;
        g_h1[idx] = v;
        __half h = __float2half_rn(v);
        g_h0h[idx] = h;
        g_h1h[idx] = h;
    }
    if (idx < Nq * Oq) g_x[idx] = lastpos[idx];
}

// ---------------- GRU combine layer 0 (fp16 gates, vectorized x4) ------------
__global__ __launch_bounds__(256, 3) void combine0(
                         const __half* __restrict__ gh,
                         float* __restrict__ h,
                         __half* __restrict__ hh,
                         const float* __restrict__ Wih0,
                         const float* __restrict__ bih,
                         const float* __restrict__ bhh)
{
    int v4 = blockIdx.x * blockDim.x + threadIdx.x;
    if (v4 >= Nq * Hq / 4) return;
    int idx = v4 * 4;
    int i = idx >> 9;
    int j = idx & (Hq - 1);

    float x0 = g_x[i * 2 + 0];
    float x1 = g_x[i * 2 + 1];

    const __half* g = gh + (size_t)i * G3;
    float gr[4], gz[4], gn[4];
    unpack4h(*(const uint2*)(g + 0 * Hq + j), gr);
    unpack4h(*(const uint2*)(g + 1 * Hq + j), gz);
    unpack4h(*(const uint2*)(g + 2 * Hq + j), gn);
    float4 br_i = *(const float4*)(bih + 0 * Hq + j);
    float4 bz_i = *(const float4*)(bih + 1 * Hq + j);
    float4 bn_i = *(const float4*)(bih + 2 * Hq + j);
    float4 br_h = *(const float4*)(bhh + 0 * Hq + j);
    float4 bz_h = *(const float4*)(bhh + 1 * Hq + j);
    float4 bn_h = *(const float4*)(bhh + 2 * Hq + j);
    float4 hp = *(const float4*)(h + idx);

    float4 wr0 = *(const float4*)(Wih0 + (0 * Hq + j) * 2);
    float4 wr1 = *(const float4*)(Wih0 + (0 * Hq + j) * 2 + 4);
    float4 wz0 = *(const float4*)(Wih0 + (1 * Hq + j) * 2);
    float4 wz1 = *(const float4*)(Wih0 + (1 * Hq + j) * 2 + 4);
    float4 wn0 = *(const float4*)(Wih0 + (2 * Hq + j) * 2);
    float4 wn1 = *(const float4*)(Wih0 + (2 * Hq + j) * 2 + 4);

    float ho[4]; __half hhv[4];
#pragma unroll
    for (int u = 0; u < 4; u++) {
        float wir0 = (u < 2) ? ((u == 0) ? wr0.x : wr0.z) : ((u == 2) ? wr1.x : wr1.z);
        float wir1 = (u < 2) ? ((u == 0) ? wr0.y : wr0.w) : ((u == 2) ? wr1.y : wr1.w);
        float wiz0 = (u < 2) ? ((u == 0) ? wz0.x : wz0.z) : ((u == 2) ? wz1.x : wz1.z);
        float wiz1 = (u < 2) ? ((u == 0) ? wz0.y : wz0.w) : ((u == 2) ? wz1.y : wz1.w);
        float win0 = (u < 2) ? ((u == 0) ? wn0.x : wn0.z) : ((u == 2) ? wn1.x : wn1.z);
        float win1 = (u < 2) ? ((u == 0) ? wn0.y : wn0.w) : ((u == 2) ? wn1.y : wn1.w);

        float ir  = x0 * wir0 + x1 * wir1 + (&br_i.x)[u];
        float iz  = x0 * wiz0 + x1 * wiz1 + (&bz_i.x)[u];
        float in_ = x0 * win0 + x1 * win1 + (&bn_i.x)[u];
        float hr = gr[u] + (&br_h.x)[u];
        float hz = gz[u] + (&bz_h.x)[u];
        float hn = gn[u] + (&bn_h.x)[u];

        float r = 1.0f / (1.0f + expf(-(ir + hr)));
        float z = 1.0f / (1.0f + expf(-(iz + hz)));
        float n = tanhf(in_ + r * hn);
        float v = (1.0f - z) * n + z * (&hp.x)[u];
        ho[u] = v;
        hhv[u] = __float2half_rn(v);
    }
    *(float4*)(h + idx) = make_float4(ho[0], ho[1], ho[2], ho[3]);
    *(uint2*)(hh + idx) = *(uint2*)hhv;
}

// ---------------- GRU combine layer 1 (fp16 gates, vectorized x4) ------------
__global__ __launch_bounds__(256, 3) void combine1(
                         const __half* __restrict__ gi,
                         const __half* __restrict__ gh,
                         float* __restrict__ h,
                         __half* __restrict__ hh,
                         const float* __restrict__ bih,
                         const float* __restrict__ bhh)
{
    int v4 = blockIdx.x * blockDim.x + threadIdx.x;
    if (v4 >= Nq * Hq / 4) return;
    int idx = v4 * 4;
    int i = idx >> 9;
    int j = idx & (Hq - 1);

    const __half* a = gi + (size_t)i * G3;
    const __half* g = gh + (size_t)i * G3;

    float ar[4], az[4], an[4], gr[4], gz[4], gn[4];
    unpack4h(*(const uint2*)(a + 0 * Hq + j), ar);
    unpack4h(*(const uint2*)(a + 1 * Hq + j), az);
    unpack4h(*(const uint2*)(a + 2 * Hq + j), an);
    unpack4h(*(const uint2*)(g + 0 * Hq + j), gr);
    unpack4h(*(const uint2*)(g + 1 * Hq + j), gz);
    unpack4h(*(const uint2*)(g + 2 * Hq + j), gn);
    float4 br_i = *(const float4*)(bih + 0 * Hq + j);
    float4 bz_i = *(const float4*)(bih + 1 * Hq + j);
    float4 bn_i = *(const float4*)(bih + 2 * Hq + j);
    float4 br_h = *(const float4*)(bhh + 0 * Hq + j);
    float4 bz_h = *(const float4*)(bhh + 1 * Hq + j);
    float4 bn_h = *(const float4*)(bhh + 2 * Hq + j);
    float4 hp = *(const float4*)(h + idx);

    float ho[4]; __half hhv[4];
#pragma unroll
    for (int u = 0; u < 4; u++) {
        float ir  = ar[u] + (&br_i.x)[u];
        float iz  = az[u] + (&bz_i.x)[u];
        float in_ = an[u] + (&bn_i.x)[u];
        float hr  = gr[u] + (&br_h.x)[u];
        float hz  = gz[u] + (&bz_h.x)[u];
        float hn  = gn[u] + (&bn_h.x)[u];

        float r = 1.0f / (1.0f + expf(-(ir + hr)));
        float z = 1.0f / (1.0f + expf(-(iz + hz)));
        float n = tanhf(in_ + r * hn);
        float v = (1.0f - z) * n + z * (&hp.x)[u];
        ho[u] = v;
        hhv[u] = __float2half_rn(v);
    }
    *(float4*)(h + idx) = make_float4(ho[0], ho[1], ho[2], ho[3]);
    *(uint2*)(hh + idx) = *(uint2*)hhv;
}

// ---------------- launch -----------------------------------------------------
extern "C" void kernel_launch(void* const* d_in, const int* in_sizes, int n_in,
                              void* d_out, int out_size)
{
    const float* social  = (const float*)d_in[0];
    const float* lastpos = (const float*)d_in[1];
    const float* Wih0    = (const float*)d_in[2];
    const float* Whh0    = (const float*)d_in[3];
    const float* bih0    = (const float*)d_in[4];
    const float* bhh0    = (const float*)d_in[5];
    const float* Wih1    = (const float*)d_in[6];
    const float* Whh1    = (const float*)d_in[7];
    const float* bih1    = (const float*)d_in[8];
    const float* bhh1    = (const float*)d_in[9];
    const float* W1      = (const float*)d_in[10];
    const float* b1      = (const float*)d_in[11];
    const float* W2      = (const float*)d_in[12];
    const float* b2      = (const float*)d_in[13];
    float* out = (float*)d_out;

    float *h0, *h1;
    __half *gate0, *gate1, *h0h, *h1h;
    __half *whh0hi, *whh0lo, *wih1hi, *wih1lo, *whh1hi, *whh1lo, *w1hi, *w1lo;
    cudaGetSymbolAddress((void**)&h0,    g_h0);
    cudaGetSymbolAddress((void**)&h1,    g_h1);
    cudaGetSymbolAddress((void**)&gate0, g_gate0);
    cudaGetSymbolAddress((void**)&gate1, g_gate1);
    cudaGetSymbolAddress((void**)&h0h,   g_h0h);
    cudaGetSymbolAddress((void**)&h1h,   g_h1h);
    cudaGetSymbolAddress((void**)&whh0hi, g_Whh0hi);
    cudaGetSymbolAddress((void**)&whh0lo, g_Whh0lo);
    cudaGetSymbolAddress((void**)&wih1hi, g_Wih1hi);
    cudaGetSymbolAddress((void**)&wih1lo, g_Wih1lo);
    cudaGetSymbolAddress((void**)&whh1hi, g_Whh1hi);
    cudaGetSymbolAddress((void**)&whh1lo, g_Whh1lo);
    cudaGetSymbolAddress((void**)&w1hi,  g_W1hi);
    cudaGetSymbolAddress((void**)&w1lo,  g_W1lo);

    cudaFuncSetAttribute(gemm_mma, cudaFuncAttributeMaxDynamicSharedMemorySize, GEMM_SMEM);
    cudaFuncSetAttribute(mlp_pred, cudaFuncAttributeMaxDynamicSharedMemorySize, MP_SMEM);

    split_all<<<(SPLIT_TOTAL + 255) / 256, 256>>>(Whh0, Wih1, Whh1, W1);
    init_kernel<<<(Nq * Hq + 255) / 256, 256>>>(social, lastpos);

    GemmProb pGh0; pGh0.a = h0h; pGh0.whi = whh0hi; pGh0.wlo = whh0lo; pGh0.C = gate0;
    GemmProb pGh1; pGh1.a = h1h; pGh1.whi = whh1hi; pGh1.wlo = whh1lo; pGh1.C = gate1;
    GemmProb pGi1; pGi1.a = h0h; pGi1.whi = wih1hi; pGi1.wlo = wih1lo; pGi1.C = gate0;

    dim3 gridDual(G3 / BN, Nq / BM, 2);
    dim3 gridSingle(G3 / BN, Nq / BM, 1);
    int combBlocks = (Nq * Hq / 4 + 255) / 256;

    for (int t = 0; t < Tq; t++) {
        gemm_mma<<<gridDual, 256, GEMM_SMEM>>>(pGh0, pGh1);
        combine0<<<combBlocks, 256>>>(gate0, h0, h0h, Wih0, bih0, bhh0);

        gemm_mma<<<gridSingle, 256, GEMM_SMEM>>>(pGi1, pGi1);
        combine1<<<combBlocks, 256>>>(gate0, gate1, h1, h1h, bih1, bhh1);

        mlp_pred<<<Nq / BM, 256, MP_SMEM>>>(h1h, w1hi, w1lo, b1, W2, b2, out, t);
    }
}